// round 6
// baseline (speedup 1.0000x reference)
#include <cuda_runtime.h>
#include <float.h>

// Problem constants (fixed by the reference: B=16, N=1024, M=21, D=256, V=16)
#define BN_TOTAL (16 * 1024)
#define MPTS 21
#define PP 20      // M-1 points per polyline
#define D1 128
#define D2 256
#define NT 256     // threads per block

typedef unsigned long long ull;

// ---- packed f32x2 helpers (Blackwell FFMA2) ----
__device__ __forceinline__ ull pack2(float x, float y) {
    ull r;
    asm("mov.b64 %0, {%1, %2};" : "=l"(r) : "f"(x), "f"(y));
    return r;
}
__device__ __forceinline__ void unpack2(ull v, float& x, float& y) {
    asm("mov.b64 {%0, %1}, %2;" : "=f"(x), "=f"(y) : "l"(v));
}
__device__ __forceinline__ ull ffma2(ull a, ull b, ull c) {
    ull d;
    asm("fma.rn.f32x2 %0, %1, %2, %3;" : "=l"(d) : "l"(a), "l"(b), "l"(c));
    return d;
}
__device__ __forceinline__ ull addf2(ull a, ull b) {
    ull d;
    asm("add.rn.f32x2 %0, %1, %2;" : "=l"(d) : "l"(a), "l"(b));
    return d;
}

__device__ float g_W23[D1 * D2];   // W2 @ W3[:256]  (128x256)
__device__ float g_bc[D2];         // b2 @ W3[:256] + b3

// Precompute W23 = W2 @ W3[:256] and bc = b2 @ W3[:256] + b3.
__global__ void precompute_w23_kernel(const float* __restrict__ W2,
                                      const float* __restrict__ W3,
                                      const float* __restrict__ b2,
                                      const float* __restrict__ b3) {
    __shared__ float rows[4][D2];
    const int blk = blockIdx.x;
    const int d = threadIdx.x;   // 0..255
    if (blk < 32) {
        #pragma unroll
        for (int r = 0; r < 4; ++r) rows[r][d] = W2[(4 * blk + r) * D2 + d];
        __syncthreads();
        float a0 = 0.f, a1 = 0.f, a2 = 0.f, a3 = 0.f;
        #pragma unroll 4
        for (int k = 0; k < D2; ++k) {
            float w = W3[k * D2 + d];
            a0 = fmaf(rows[0][k], w, a0);
            a1 = fmaf(rows[1][k], w, a1);
            a2 = fmaf(rows[2][k], w, a2);
            a3 = fmaf(rows[3][k], w, a3);
        }
        g_W23[(4 * blk + 0) * D2 + d] = a0;
        g_W23[(4 * blk + 1) * D2 + d] = a1;
        g_W23[(4 * blk + 2) * D2 + d] = a2;
        g_W23[(4 * blk + 3) * D2 + d] = a3;
    } else {
        rows[0][d] = b2[d];
        __syncthreads();
        float a = 0.f;
        #pragma unroll 4
        for (int k = 0; k < D2; ++k) a = fmaf(rows[0][k], W3[k * D2 + d], a);
        g_bc[d] = a + b3[d];
    }
}

__global__ __launch_bounds__(NT, 3) void map_encoder_kernel(
    const float* __restrict__ tgt,      // (B,N,21,2)
    const int* __restrict__ label,      // (B,N)
    const void* __restrict__ maskp,     // (B,N) bool or int32
    const float* __restrict__ W1, const float* __restrict__ b1,
    const float* __restrict__ g1, const float* __restrict__ be1,
    const float* __restrict__ m1, const float* __restrict__ v1,
    const float* __restrict__ W2, const float* __restrict__ b2,
    const float* __restrict__ W3, const float* __restrict__ b3,
    const float* __restrict__ g2, const float* __restrict__ be2,
    const float* __restrict__ m2, const float* __restrict__ v2,
    const float* __restrict__ W4, const float* __restrict__ b4,
    const float* __restrict__ temb,     // (16,256)
    const float* __restrict__ Wp1, const float* __restrict__ bp1,
    const float* __restrict__ Wp2, const float* __restrict__ bp2,
    const float* __restrict__ pcr,      // (6,)
    float* __restrict__ out)
{
    // [channel][point] transposed; 20-float (80B) rows, halves 8B-aligned.
    __shared__ __align__(16) float sm_h1T[D1 * PP];  // 10KB; scratch/hp later
    __shared__ __align__(16) float sm_h2T[D2 * PP];  // 20KB; exchange buf later
    __shared__ __align__(16) float sm_vec[D2];       // pooled -> sine
    __shared__ float sm_pts[MPTS * 2 + 2];
    __shared__ float sm_feat[PP * 6];

    const int idx = blockIdx.x;
    const int t = threadIdx.x;          // 0..255

    // ---- inline mask-dtype detection: any nonzero byte at addr%4!=0 in the
    // first 256 bytes => byte-bool mask (int32 0/1 data has none there). ----
    int f = 0;
    if (t < 64) {
        unsigned v = ((const unsigned*)maskp)[t];
        f = (v & 0xFFFFFF00u) ? 1 : 0;
    }
    int isbyte = __syncthreads_or(f);

    bool mask;
    if (isbyte) mask = ((const unsigned char*)maskp)[idx] != 0;
    else        mask = ((const int*)maskp)[idx] != 0;

    float* __restrict__ feats_out = out;
    float* __restrict__ pos_out   = out + (size_t)BN_TOTAL * D2;
    float* __restrict__ mask_out  = out + (size_t)2 * BN_TOTAL * D2;

    if (!mask) {
        if (t < 128) *(float2*)&feats_out[(size_t)idx * D2 + 2 * t] = make_float2(0.f, 0.f);
        else         *(float2*)&pos_out[(size_t)idx * D2 + 2 * (t - 128)] = make_float2(0.f, 0.f);
        if (t == 0) mask_out[idx] = 1.0f;
        return;
    }
    if (t == 0) mask_out[idx] = 0.0f;

    // ---- load points ----
    const float* ppin = tgt + (size_t)idx * MPTS * 2;
    if (t < MPTS * 2) sm_pts[t] = ppin[t];
    __syncthreads();

    // ---- feature construction ----
    if (t < PP) {
        int p = t;
        float cx = sm_pts[10 * 2], cy = sm_pts[10 * 2 + 1];
        float x0 = sm_pts[2 * p],     y0 = sm_pts[2 * p + 1];
        float x1 = sm_pts[2 * p + 2], y1 = sm_pts[2 * p + 3];
        float pvx = x1 - x0, pvy = y1 - y0;
        float vn = sqrtf(pvx * pvx + pvy * pvy) + 1.0f + 1e-6f;
        float inv = 1.0f / vn;
        sm_feat[p * 6 + 0] = x0 - cx;
        sm_feat[p * 6 + 1] = y0 - cy;
        sm_feat[p * 6 + 2] = pvx;
        sm_feat[p * 6 + 3] = pvy;
        sm_feat[p * 6 + 4] = pvx * inv;
        sm_feat[p * 6 + 5] = pvy * inv;
    }
    __syncthreads();

    const int cp = t & 127;   // column pair: cols 2cp, 2cp+1
    const int ph = t >> 7;    // point half: points [10ph, 10ph+10)

    // ---- stage 1: feat(20x6)@W1+b1 -> BN1 -> relu -> sm_h1T ----
    // thread (d=cp, ph) computes channel cp for its 10 points (d<128)
    {
        int d = cp;
        float w0 = W1[0 * D1 + d], w1 = W1[1 * D1 + d], w2 = W1[2 * D1 + d];
        float w3 = W1[3 * D1 + d], w4 = W1[4 * D1 + d], w5 = W1[5 * D1 + d];
        float s  = g1[d] * rsqrtf(v1[d] + 1e-5f);
        float sh = be1[d] - m1[d] * s + b1[d] * s;
        #pragma unroll
        for (int q = 0; q < 10; ++q) {
            int p = ph * 10 + q;
            const float* fv = &sm_feat[p * 6];
            float lin = fv[0] * w0 + fv[1] * w1 + fv[2] * w2
                      + fv[3] * w3 + fv[4] * w4 + fv[5] * w5;
            sm_h1T[d * PP + p] = fmaxf(lin * s + sh, 0.0f);
        }
    }
    __syncthreads();

    // ---- FUSED stage2 (h1@W2 -> pooled max) + stage3 h-term (h1@W23) ----
    // One h1-row read feeds both weight sets. Thread: 2 cols x 10 points.
    ull a3[10];   // h1@W23 accumulators (kept live into stage-3 epilogue)
    {
        ull a2[10];
        #pragma unroll
        for (int q = 0; q < 10; ++q) { a2[q] = 0ull; a3[q] = 0ull; }
        #pragma unroll 2
        for (int c = 0; c < D1; ++c) {
            float2 w2v = *(const float2*)(W2 + c * D2 + 2 * cp);
            float2 w3v = *(const float2*)(g_W23 + c * D2 + 2 * cp);
            ull w20 = pack2(w2v.x, w2v.x), w21 = pack2(w2v.y, w2v.y);
            ull w30 = pack2(w3v.x, w3v.x), w31 = pack2(w3v.y, w3v.y);
            const ull* hv = (const ull*)(sm_h1T + c * PP + ph * 10);
            #pragma unroll
            for (int q = 0; q < 5; ++q) {
                ull h = hv[q];
                a2[q]     = ffma2(h, w20, a2[q]);
                a2[5 + q] = ffma2(h, w21, a2[5 + q]);
                a3[q]     = ffma2(h, w30, a3[q]);
                a3[5 + q] = ffma2(h, w31, a3[5 + q]);
            }
        }
        // per-thread max over own 10 points, per column
        float mx0 = -FLT_MAX, mx1 = -FLT_MAX;
        #pragma unroll
        for (int q = 0; q < 5; ++q) {
            float a, b;
            unpack2(a2[q], a, b);     mx0 = fmaxf(mx0, fmaxf(a, b));
            unpack2(a2[5 + q], a, b); mx1 = fmaxf(mx1, fmaxf(a, b));
        }
        // scratch: first 512 floats of sm_h2T (real h2T written later)
        *(float2*)&sm_h2T[ph * D2 + 2 * cp] = make_float2(mx0, mx1);
    }
    __syncthreads();
    // pooled[d] = max over both point-halves + b2[d]
    sm_vec[t] = fmaxf(sm_h2T[t], sm_h2T[D2 + t]) + b2[t];
    __syncthreads();

    // ---- stage 3 epilogue: base = pooled@W3[256:] (c split by ph) + bc ----
    float bx, by;
    {
        ull bacc = 0ull;
        #pragma unroll 2
        for (int k = 0; k < 128; ++k) {
            int c = ph * 128 + k;
            ull wb = *(const ull*)(W3 + (size_t)(D2 + c) * D2 + 2 * cp);
            float pc = sm_vec[c];
            bacc = ffma2(wb, pack2(pc, pc), bacc);
        }
        ((ull*)sm_h1T)[t] = bacc;   // h1T dead -> exchange scratch (2KB)
        __syncthreads();
        ull btot = addf2(bacc, ((const ull*)sm_h1T)[t ^ 128]);
        unpack2(btot, bx, by);
        float2 bcv = *(const float2*)(g_bc + 2 * cp);
        bx += bcv.x; by += bcv.y;
    }

    // BN2 + relu -> write h2T (disjoint: 2 cols x 10 points per thread)
    {
        float2 gg = *(const float2*)(g2  + 2 * cp);
        float2 vv = *(const float2*)(v2  + 2 * cp);
        float2 mm = *(const float2*)(m2  + 2 * cp);
        float2 ee = *(const float2*)(be2 + 2 * cp);
        float s0 = gg.x * rsqrtf(vv.x + 1e-5f);
        float s1 = gg.y * rsqrtf(vv.y + 1e-5f);
        float sh0 = ee.x - mm.x * s0;
        float sh1 = ee.y - mm.y * s1;
        float* r0 = sm_h2T + (2 * cp) * PP + ph * 10;
        float* r1 = r0 + PP;
        #pragma unroll
        for (int q = 0; q < 5; ++q) {
            float a, b;
            unpack2(a3[q], a, b);
            *(float2*)&r0[2 * q] =
                make_float2(fmaxf((a + bx) * s0 + sh0, 0.0f),
                            fmaxf((b + bx) * s0 + sh0, 0.0f));
            unpack2(a3[5 + q], a, b);
            *(float2*)&r1[2 * q] =
                make_float2(fmaxf((a + by) * s1 + sh1, 0.0f),
                            fmaxf((b + by) * s1 + sh1, 0.0f));
        }
    }
    __syncthreads();

    // ---- stage 4: h2(20x256)@W4+b4 -> max_p -> +temb ----
    // Thread: 4 cols x 10 pts x half of c. 1 LDG.128 + 5 LDS.64 per 20 FFMA2.
    {
        const int cp4 = t & 63;          // cols 4cp4..4cp4+3
        const int ph4 = (t >> 6) & 1;    // point half
        const int ch  = t >> 7;          // c half
        ull a[4][5];
        #pragma unroll
        for (int j = 0; j < 4; ++j)
            #pragma unroll
            for (int q = 0; q < 5; ++q) a[j][q] = 0ull;
        #pragma unroll 2
        for (int k = 0; k < 128; ++k) {
            int c = ch * 128 + k;
            float4 w = *(const float4*)(W4 + c * D2 + 4 * cp4);
            ull w0 = pack2(w.x, w.x), w1 = pack2(w.y, w.y);
            ull w2v = pack2(w.z, w.z), w3v = pack2(w.w, w.w);
            const ull* hv = (const ull*)(sm_h2T + c * PP + ph4 * 10);
            #pragma unroll
            for (int q = 0; q < 5; ++q) {
                ull h = hv[q];
                a[0][q] = ffma2(h, w0, a[0][q]);
                a[1][q] = ffma2(h, w1, a[1][q]);
                a[2][q] = ffma2(h, w2v, a[2][q]);
                a[3][q] = ffma2(h, w3v, a[3][q]);
            }
        }
        __syncthreads();   // all h2T reads complete
        if (ch == 1) {     // upper c-half dumps partials into (now dead) h2T
            ull* dst = (ull*)sm_h2T + (t - 128) * 20;
            #pragma unroll
            for (int j = 0; j < 4; ++j)
                #pragma unroll
                for (int q = 0; q < 5; ++q) dst[j * 5 + q] = a[j][q];
        }
        __syncthreads();
        if (ch == 0) {     // combine halves, max over own 10 points
            const ull* src = (const ull*)sm_h2T + t * 20;
            float mx[4];
            #pragma unroll
            for (int j = 0; j < 4; ++j) {
                float m = -FLT_MAX;
                #pragma unroll
                for (int q = 0; q < 5; ++q) {
                    ull s = addf2(a[j][q], src[j * 5 + q]);
                    float x, y;
                    unpack2(s, x, y);
                    m = fmaxf(m, fmaxf(x, y));
                }
                mx[j] = m;
            }
            // scratch in (dead) sm_h1T: slot (cp4, ph4)
            *(float4*)&sm_h1T[cp4 * 8 + ph4 * 4] =
                make_float4(mx[0], mx[1], mx[2], mx[3]);
        }
        __syncthreads();
        if (t < 64) {
            float4 mA = *(const float4*)&sm_h1T[t * 8];
            float4 mB = *(const float4*)&sm_h1T[t * 8 + 4];
            float4 bb = *(const float4*)(b4 + 4 * t);
            int lb = label[idx];
            float4 tv = *(const float4*)(temb + (size_t)lb * D2 + 4 * t);
            *(float4*)&feats_out[(size_t)idx * D2 + 4 * t] =
                make_float4(fmaxf(mA.x, mB.x) + bb.x + tv.x,
                            fmaxf(mA.y, mB.y) + bb.y + tv.y,
                            fmaxf(mA.z, mB.z) + bb.z + tv.z,
                            fmaxf(mA.w, mB.w) + bb.w + tv.w);
        }
    }

    // ---- sine embedding: thread t -> sine[t] (sm_vec pooled is dead) ----
    {
        float c0 = pcr[0], c1 = pcr[1], c3 = pcr[3], c4 = pcr[4];
        float posx = (sm_pts[10 * 2]     - c0) / (c3 - c0);
        float posy = (sm_pts[10 * 2 + 1] - c1) / (c4 - c1);
        int j = t & 127;
        float pos = (t < 128) ? posy : posx;
        int i = j >> 1;
        float freq = powf(10000.0f, (float)i * (1.0f / 64.0f));
        float arg = pos * 6.283185307179586f / freq;
        sm_vec[t] = (j & 1) ? cosf(arg) : sinf(arg);
    }
    __syncthreads();   // fences: h1T scratch reads (t<64), sine writes

    // ---- hp = relu(sine @ Wp1(256x512) + bp1): thread t -> cols 2t, 2t+1 ----
    {
        ull acc = pack2(bp1[2 * t], bp1[2 * t + 1]);
        #pragma unroll 4
        for (int j = 0; j < 256; ++j) {
            float sv = sm_vec[j];
            acc = ffma2(*(const ull*)(Wp1 + j * 512 + 2 * t), pack2(sv, sv), acc);
        }
        float a, b;
        unpack2(acc, a, b);
        *(float2*)&sm_h1T[2 * t] = make_float2(fmaxf(a, 0.0f), fmaxf(b, 0.0f));
    }
    __syncthreads();

    // ---- pe = hp @ Wp2(512x256) + bp2: 2 cols, c split by half ----
    {
        int cc = t & 127;    // cols 2cc, 2cc+1
        int ch = t >> 7;     // k half
        ull acc = 0ull;
        #pragma unroll 4
        for (int k = 0; k < 256; ++k) {
            int c = ch * 256 + k;
            float hk = sm_h1T[c];
            acc = ffma2(*(const ull*)(Wp2 + c * D2 + 2 * cc), pack2(hk, hk), acc);
        }
        ((ull*)sm_h2T)[t] = acc;   // h2T dead -> exchange
        __syncthreads();
        if (t < 128) {
            ull tot = addf2(acc, ((const ull*)sm_h2T)[t + 128]);
            float a, b;
            unpack2(tot, a, b);
            *(float2*)&pos_out[(size_t)idx * D2 + 2 * t] =
                make_float2(a + bp2[2 * t], b + bp2[2 * t + 1]);
        }
    }
}

extern "C" void kernel_launch(void* const* d_in, const int* in_sizes, int n_in,
                              void* d_out, int out_size) {
    (void)in_sizes; (void)n_in; (void)out_size;

    const float* tgt   = (const float*)d_in[0];
    const int*   label = (const int*)d_in[1];
    const void*  maskp = d_in[2];
    const float* W1  = (const float*)d_in[3];
    const float* b1  = (const float*)d_in[4];
    const float* g1  = (const float*)d_in[5];
    const float* be1 = (const float*)d_in[6];
    const float* m1  = (const float*)d_in[7];
    const float* v1  = (const float*)d_in[8];
    const float* W2  = (const float*)d_in[9];
    const float* b2  = (const float*)d_in[10];
    const float* W3  = (const float*)d_in[11];
    const float* b3  = (const float*)d_in[12];
    const float* g2  = (const float*)d_in[13];
    const float* be2 = (const float*)d_in[14];
    const float* m2  = (const float*)d_in[15];
    const float* v2  = (const float*)d_in[16];
    const float* W4  = (const float*)d_in[17];
    const float* b4  = (const float*)d_in[18];
    const float* temb = (const float*)d_in[19];
    const float* Wp1 = (const float*)d_in[20];
    const float* bp1 = (const float*)d_in[21];
    const float* Wp2 = (const float*)d_in[22];
    const float* bp2 = (const float*)d_in[23];
    const float* pcr = (const float*)d_in[24];

    precompute_w23_kernel<<<33, 256>>>(W2, W3, b2, b3);
    map_encoder_kernel<<<BN_TOTAL, NT>>>(
        tgt, label, maskp,
        W1, b1, g1, be1, m1, v1,
        W2, b2, W3, b3, g2, be2, m2, v2,
        W4, b4, temb, Wp1, bp1, Wp2, bp2, pcr,
        (float*)d_out);
}

// round 7
// speedup vs baseline: 1.3631x; 1.3631x over previous
#include <cuda_runtime.h>
#include <float.h>

// Problem constants (fixed by the reference: B=16, N=1024, M=21, D=256, V=16)
#define BN_TOTAL (16 * 1024)
#define MPTS 21
#define PP 20      // M-1 points per polyline
#define D1 128
#define D2 256

typedef unsigned long long ull;

// ---- packed f32x2 helpers (Blackwell FFMA2) ----
__device__ __forceinline__ ull pack2(float x, float y) {
    ull r;
    asm("mov.b64 %0, {%1, %2};" : "=l"(r) : "f"(x), "f"(y));
    return r;
}
__device__ __forceinline__ void unpack2(ull v, float& x, float& y) {
    asm("mov.b64 {%0, %1}, %2;" : "=f"(x), "=f"(y) : "l"(v));
}
__device__ __forceinline__ ull ffma2(ull a, ull b, ull c) {
    ull d;
    asm("fma.rn.f32x2 %0, %1, %2, %3;" : "=l"(d) : "l"(a), "l"(b), "l"(c));
    return d;
}

__device__ float g_W23[D1 * D2];   // W2 @ W3[:256]  (128x256)
__device__ float g_bc[D2];         // b2 @ W3[:256] + b3
__device__ float g_scale[D2];      // sine arg multiplier per channel
__device__ int   g_count;
__device__ int   g_active[BN_TOTAL];
__device__ float g_hp[(size_t)BN_TOTAL * 512];   // PE hidden activations

// ---- precompute: W23, bc, sine scale table, zero active-count ----
__global__ void precompute_w23_kernel(const float* __restrict__ W2,
                                      const float* __restrict__ W3,
                                      const float* __restrict__ b2,
                                      const float* __restrict__ b3) {
    __shared__ float rows[4][D2];
    const int blk = blockIdx.x;
    const int d = threadIdx.x;   // 0..255
    if (blk < 32) {
        #pragma unroll
        for (int r = 0; r < 4; ++r) rows[r][d] = W2[(4 * blk + r) * D2 + d];
        __syncthreads();
        float a0 = 0.f, a1 = 0.f, a2 = 0.f, a3 = 0.f;
        #pragma unroll 4
        for (int k = 0; k < D2; ++k) {
            float w = W3[k * D2 + d];
            a0 = fmaf(rows[0][k], w, a0);
            a1 = fmaf(rows[1][k], w, a1);
            a2 = fmaf(rows[2][k], w, a2);
            a3 = fmaf(rows[3][k], w, a3);
        }
        g_W23[(4 * blk + 0) * D2 + d] = a0;
        g_W23[(4 * blk + 1) * D2 + d] = a1;
        g_W23[(4 * blk + 2) * D2 + d] = a2;
        g_W23[(4 * blk + 3) * D2 + d] = a3;
    } else {
        rows[0][d] = b2[d];
        __syncthreads();
        float a = 0.f;
        #pragma unroll 4
        for (int k = 0; k < D2; ++k) a = fmaf(rows[0][k], W3[k * D2 + d], a);
        g_bc[d] = a + b3[d];
        // sine scale table: channel d -> 2*pi / 10000^(i/64), i = (d&127)>>1
        int i = (d & 127) >> 1;
        float freq = powf(10000.0f, (float)i * (1.0f / 64.0f));
        g_scale[d] = 6.283185307179586f / freq;
        if (d == 0) g_count = 0;
    }
}

// ---- build compacted active-polyline list ----
__global__ void build_active_kernel(const void* __restrict__ maskp) {
    const int t = threadIdx.x;
    const int i = blockIdx.x * 256 + t;
    int f = 0;
    if (t < 64) {
        unsigned v = ((const unsigned*)maskp)[t];
        f = (v & 0xFFFFFF00u) ? 1 : 0;
    }
    int isbyte = __syncthreads_or(f);
    bool m = isbyte ? (((const unsigned char*)maskp)[i] != 0)
                    : (((const int*)maskp)[i] != 0);
    if (m) {
        int p = atomicAdd(&g_count, 1);
        g_active[p] = i;
    }
}

// ---- main per-polyline kernel (map_feats path only; PE split out) ----
// 128 threads. Thread t owns cols (2t, 2t+1), all 20 points. Stage2 (h1@W2
// for pooled max) and stage3's h-term (h1@W23) are fused over one h1-row read.
__global__ __launch_bounds__(128, 4) void map_encoder_kernel(
    const float* __restrict__ tgt,      // (B,N,21,2)
    const int* __restrict__ label,      // (B,N)
    const void* __restrict__ maskp,     // (B,N) bool or int32
    const float* __restrict__ W1, const float* __restrict__ b1,
    const float* __restrict__ g1, const float* __restrict__ be1,
    const float* __restrict__ m1, const float* __restrict__ v1,
    const float* __restrict__ W2, const float* __restrict__ b2,
    const float* __restrict__ W3,
    const float* __restrict__ g2, const float* __restrict__ be2,
    const float* __restrict__ m2, const float* __restrict__ v2,
    const float* __restrict__ W4, const float* __restrict__ b4,
    const float* __restrict__ temb,     // (16,256)
    float* __restrict__ out)
{
    __shared__ __align__(16) float sm_h1T[D1 * PP];  // 10 KB
    __shared__ __align__(16) float sm_h2T[D2 * PP];  // 20 KB
    __shared__ __align__(16) float sm_vec[D2];       // pooled
    __shared__ float sm_pts[MPTS * 2 + 2];
    __shared__ float sm_feat[PP * 6];

    const int idx = blockIdx.x;
    const int t = threadIdx.x;          // 0..127

    // inline mask-dtype detection (uniform across grid)
    int f = 0;
    if (t < 64) {
        unsigned v = ((const unsigned*)maskp)[t];
        f = (v & 0xFFFFFF00u) ? 1 : 0;
    }
    int isbyte = __syncthreads_or(f);
    bool mask = isbyte ? (((const unsigned char*)maskp)[idx] != 0)
                       : (((const int*)maskp)[idx] != 0);

    float* __restrict__ feats_out = out;
    float* __restrict__ pos_out   = out + (size_t)BN_TOTAL * D2;
    float* __restrict__ mask_out  = out + (size_t)2 * BN_TOTAL * D2;

    if (!mask) {
        *(float2*)&feats_out[(size_t)idx * D2 + 2 * t] = make_float2(0.f, 0.f);
        *(float2*)&pos_out[(size_t)idx * D2 + 2 * t]   = make_float2(0.f, 0.f);
        if (t == 0) mask_out[idx] = 1.0f;
        return;
    }
    if (t == 0) mask_out[idx] = 0.0f;

    // ---- load points ----
    const float* ppin = tgt + (size_t)idx * MPTS * 2;
    if (t < MPTS * 2) sm_pts[t] = ppin[t];
    __syncthreads();

    // ---- feature construction ----
    if (t < PP) {
        int p = t;
        float cx = sm_pts[10 * 2], cy = sm_pts[10 * 2 + 1];
        float x0 = sm_pts[2 * p],     y0 = sm_pts[2 * p + 1];
        float x1 = sm_pts[2 * p + 2], y1 = sm_pts[2 * p + 3];
        float pvx = x1 - x0, pvy = y1 - y0;
        float vn = sqrtf(pvx * pvx + pvy * pvy) + 1.0f + 1e-6f;
        float inv = 1.0f / vn;
        sm_feat[p * 6 + 0] = x0 - cx;
        sm_feat[p * 6 + 1] = y0 - cy;
        sm_feat[p * 6 + 2] = pvx;
        sm_feat[p * 6 + 3] = pvy;
        sm_feat[p * 6 + 4] = pvx * inv;
        sm_feat[p * 6 + 5] = pvy * inv;
    }
    __syncthreads();

    // ---- stage 1: feat(20x6)@W1+b1 -> BN1 -> relu -> sm_h1T ----
    {
        int d = t;
        float w0 = W1[0 * D1 + d], w1 = W1[1 * D1 + d], w2 = W1[2 * D1 + d];
        float w3 = W1[3 * D1 + d], w4 = W1[4 * D1 + d], w5 = W1[5 * D1 + d];
        float s  = g1[d] * rsqrtf(v1[d] + 1e-5f);
        float sh = be1[d] - m1[d] * s + b1[d] * s;
        #pragma unroll
        for (int p = 0; p < PP; ++p) {
            const float* fv = &sm_feat[p * 6];
            float lin = fv[0] * w0 + fv[1] * w1 + fv[2] * w2
                      + fv[3] * w3 + fv[4] * w4 + fv[5] * w5;
            sm_h1T[d * PP + p] = fmaxf(lin * s + sh, 0.0f);
        }
    }
    __syncthreads();

    // ---- FUSED stage2 (h1@W2 -> pooled) + stage3 h-term (h1@W23) ----
    ull a3c0[10], a3c1[10];   // kept live into the stage-3 epilogue
    {
        ull a2c0[10], a2c1[10];
        #pragma unroll
        for (int q = 0; q < 10; ++q) {
            a2c0[q] = 0ull; a2c1[q] = 0ull; a3c0[q] = 0ull; a3c1[q] = 0ull;
        }
        #pragma unroll 2
        for (int c = 0; c < D1; ++c) {
            float2 w2v = *(const float2*)(W2 + c * D2 + 2 * t);
            float2 w3v = *(const float2*)(g_W23 + c * D2 + 2 * t);
            ull w20 = pack2(w2v.x, w2v.x), w21 = pack2(w2v.y, w2v.y);
            ull w30 = pack2(w3v.x, w3v.x), w31 = pack2(w3v.y, w3v.y);
            const ulonglong2* hv = (const ulonglong2*)(sm_h1T + c * PP);
            #pragma unroll
            for (int q = 0; q < 5; ++q) {
                ulonglong2 h = hv[q];
                a2c0[2 * q]     = ffma2(h.x, w20, a2c0[2 * q]);
                a2c0[2 * q + 1] = ffma2(h.y, w20, a2c0[2 * q + 1]);
                a2c1[2 * q]     = ffma2(h.x, w21, a2c1[2 * q]);
                a2c1[2 * q + 1] = ffma2(h.y, w21, a2c1[2 * q + 1]);
                a3c0[2 * q]     = ffma2(h.x, w30, a3c0[2 * q]);
                a3c0[2 * q + 1] = ffma2(h.y, w30, a3c0[2 * q + 1]);
                a3c1[2 * q]     = ffma2(h.x, w31, a3c1[2 * q]);
                a3c1[2 * q + 1] = ffma2(h.y, w31, a3c1[2 * q + 1]);
            }
        }
        float2 bb = *(const float2*)(b2 + 2 * t);
        float mx0 = -FLT_MAX, mx1 = -FLT_MAX;
        #pragma unroll
        for (int q = 0; q < 10; ++q) {
            float a, b;
            unpack2(a2c0[q], a, b); mx0 = fmaxf(mx0, fmaxf(a, b));
            unpack2(a2c1[q], a, b); mx1 = fmaxf(mx1, fmaxf(a, b));
        }
        *(float2*)&sm_vec[2 * t] = make_float2(mx0 + bb.x, mx1 + bb.y);
    }
    __syncthreads();

    // ---- stage 3 epilogue: base = pooled@W3[256:] + bc; BN2+relu -> h2T ----
    {
        ull base = 0ull;
        #pragma unroll 4
        for (int c = 0; c < D2; ++c) {
            ull wb = *(const ull*)(W3 + (size_t)(D2 + c) * D2 + 2 * t);
            float pc = sm_vec[c];
            base = ffma2(wb, pack2(pc, pc), base);
        }
        float bx, by;
        unpack2(base, bx, by);
        float2 bcv = *(const float2*)(g_bc + 2 * t);
        bx += bcv.x; by += bcv.y;

        float2 gg = *(const float2*)(g2  + 2 * t);
        float2 vv = *(const float2*)(v2  + 2 * t);
        float2 mm = *(const float2*)(m2  + 2 * t);
        float2 ee = *(const float2*)(be2 + 2 * t);
        float s0 = gg.x * rsqrtf(vv.x + 1e-5f);
        float s1 = gg.y * rsqrtf(vv.y + 1e-5f);
        float sh0 = ee.x - mm.x * s0;
        float sh1 = ee.y - mm.y * s1;
        float* r0 = sm_h2T + (2 * t) * PP;
        float* r1 = sm_h2T + (2 * t + 1) * PP;
        #pragma unroll
        for (int q = 0; q < 10; ++q) {
            float a, b;
            unpack2(a3c0[q], a, b);
            *(float2*)&r0[2 * q] =
                make_float2(fmaxf((a + bx) * s0 + sh0, 0.0f),
                            fmaxf((b + bx) * s0 + sh0, 0.0f));
            unpack2(a3c1[q], a, b);
            *(float2*)&r1[2 * q] =
                make_float2(fmaxf((a + by) * s1 + sh1, 0.0f),
                            fmaxf((b + by) * s1 + sh1, 0.0f));
        }
    }
    __syncthreads();

    // ---- stage 4: h2(20x256)@W4+b4 -> max_p -> +type_emb -> out ----
    {
        ull acc0[10], acc1[10];
        #pragma unroll
        for (int q = 0; q < 10; ++q) { acc0[q] = 0ull; acc1[q] = 0ull; }
        #pragma unroll 2
        for (int c = 0; c < D2; ++c) {
            float2 w = *(const float2*)(W4 + c * D2 + 2 * t);
            ull w0 = pack2(w.x, w.x);
            ull w1 = pack2(w.y, w.y);
            const ulonglong2* hv = (const ulonglong2*)(sm_h2T + c * PP);
            #pragma unroll
            for (int q = 0; q < 5; ++q) {
                ulonglong2 h = hv[q];
                acc0[2 * q]     = ffma2(h.x, w0, acc0[2 * q]);
                acc0[2 * q + 1] = ffma2(h.y, w0, acc0[2 * q + 1]);
                acc1[2 * q]     = ffma2(h.x, w1, acc1[2 * q]);
                acc1[2 * q + 1] = ffma2(h.y, w1, acc1[2 * q + 1]);
            }
        }
        float2 bb = *(const float2*)(b4 + 2 * t);
        float mx0 = -FLT_MAX, mx1 = -FLT_MAX;
        #pragma unroll
        for (int q = 0; q < 10; ++q) {
            float a, b;
            unpack2(acc0[q], a, b); mx0 = fmaxf(mx0, fmaxf(a, b));
            unpack2(acc1[q], a, b); mx1 = fmaxf(mx1, fmaxf(a, b));
        }
        int lb = label[idx];
        float2 tv = *(const float2*)(temb + (size_t)lb * D2 + 2 * t);
        *(float2*)&feats_out[(size_t)idx * D2 + 2 * t] =
            make_float2(mx0 + bb.x + tv.x, mx1 + bb.y + tv.y);
    }
}

// ---- PE stage A: hp = relu(sine @ Wp1 + bp1), batched 16 actives/block ----
__global__ __launch_bounds__(256) void pe_a_kernel(
    const float* __restrict__ tgt, const float* __restrict__ Wp1,
    const float* __restrict__ bp1, const float* __restrict__ pcr)
{
    __shared__ __align__(16) float s_sine[D2 * 16];   // [c][r], 16 KB
    __shared__ float s_pos[2][16];                    // [0]=posy [1]=posx

    const int base = blockIdx.x * 16;
    int nb = g_count - base;
    if (nb <= 0) return;
    if (nb > 16) nb = 16;
    const int t = threadIdx.x;

    if (t < 32) {
        int r = t & 15, xy = t >> 4;
        int poly = g_active[base + ((r < nb) ? r : 0)];
        float cv = tgt[(size_t)poly * (MPTS * 2) + 20 + xy];
        float lo = pcr[xy], hi = pcr[3 + xy];
        s_pos[1 - xy][r] = (cv - lo) / (hi - lo);   // xy=0 (x) -> posx slot 1
    }
    __syncthreads();

    // sine: thread (r = t&15, cg = t>>4) computes 16 channels for its row
    {
        int r = t & 15, cg = t >> 4;
        float py = s_pos[0][r], px = s_pos[1][r];
        #pragma unroll
        for (int j = 0; j < 16; ++j) {
            int c = cg + 16 * j;
            float pos = (c < 128) ? py : px;
            float arg = pos * g_scale[c];
            s_sine[c * 16 + r] = (c & 1) ? cosf(arg) : sinf(arg);
        }
    }
    __syncthreads();

    // hp: thread t -> cols (2t, 2t+1) of 512, all 16 rows
    ull a0[8], a1[8];
    {
        float2 bb = *(const float2*)(bp1 + 2 * t);
        #pragma unroll
        for (int q = 0; q < 8; ++q) { a0[q] = pack2(bb.x, bb.x); a1[q] = pack2(bb.y, bb.y); }
    }
    #pragma unroll 2
    for (int c = 0; c < D2; ++c) {
        float2 w = *(const float2*)(Wp1 + c * 512 + 2 * t);
        ull w0 = pack2(w.x, w.x), w1 = pack2(w.y, w.y);
        const ulonglong2* sv = (const ulonglong2*)(s_sine + c * 16);
        #pragma unroll
        for (int q = 0; q < 4; ++q) {
            ulonglong2 h = sv[q];
            a0[2 * q]     = ffma2(h.x, w0, a0[2 * q]);
            a0[2 * q + 1] = ffma2(h.y, w0, a0[2 * q + 1]);
            a1[2 * q]     = ffma2(h.x, w1, a1[2 * q]);
            a1[2 * q + 1] = ffma2(h.y, w1, a1[2 * q + 1]);
        }
    }
    #pragma unroll
    for (int q = 0; q < 8; ++q) {
        float x0, y0, x1, y1;
        unpack2(a0[q], x0, y0);   // rows 2q, 2q+1 for col 2t
        unpack2(a1[q], x1, y1);   // rows 2q, 2q+1 for col 2t+1
        int r0 = 2 * q, r1 = 2 * q + 1;
        if (r0 < nb)
            *(float2*)&g_hp[(size_t)(base + r0) * 512 + 2 * t] =
                make_float2(fmaxf(x0, 0.f), fmaxf(x1, 0.f));
        if (r1 < nb)
            *(float2*)&g_hp[(size_t)(base + r1) * 512 + 2 * t] =
                make_float2(fmaxf(y0, 0.f), fmaxf(y1, 0.f));
    }
}

// ---- PE stage B: pe = hp @ Wp2 + bp2 -> pos_out, batched 16/block ----
__global__ __launch_bounds__(256) void pe_b_kernel(
    const float* __restrict__ Wp2, const float* __restrict__ bp2,
    float* __restrict__ out)
{
    __shared__ __align__(16) float s_hp[512 * 16];   // [k][r], 32 KB

    const int base = blockIdx.x * 16;
    int nb = g_count - base;
    if (nb <= 0) return;
    if (nb > 16) nb = 16;
    const int t = threadIdx.x;
    float* __restrict__ pos_out = out + (size_t)BN_TOTAL * D2;

    // load + transpose: thread (r = t&15, kg = t>>4) loads 32 k-values
    {
        int r = t & 15, kg = t >> 4;
        int rr = (r < nb) ? r : 0;
        const float* src = g_hp + (size_t)(base + rr) * 512 + kg * 32;
        #pragma unroll
        for (int jj = 0; jj < 8; ++jj) {
            float4 v = *(const float4*)(src + jj * 4);
            int k = kg * 32 + jj * 4;
            s_hp[(k + 0) * 16 + r] = v.x;
            s_hp[(k + 1) * 16 + r] = v.y;
            s_hp[(k + 2) * 16 + r] = v.z;
            s_hp[(k + 3) * 16 + r] = v.w;
        }
    }
    __syncthreads();

    // pe: thread (cc = t&127 -> cols 2cc,2cc+1 ; rh = t>>7 -> rows rh*8..+8)
    const int cc = t & 127, rh = t >> 7;
    ull a0[4], a1[4];
    {
        float2 bb = *(const float2*)(bp2 + 2 * cc);
        #pragma unroll
        for (int q = 0; q < 4; ++q) { a0[q] = pack2(bb.x, bb.x); a1[q] = pack2(bb.y, bb.y); }
    }
    #pragma unroll 4
    for (int k = 0; k < 512; ++k) {
        float2 w = *(const float2*)(Wp2 + k * D2 + 2 * cc);
        ull w0 = pack2(w.x, w.x), w1 = pack2(w.y, w.y);
        const ulonglong2* hv = (const ulonglong2*)(s_hp + k * 16 + rh * 8);
        ulonglong2 h0 = hv[0];   // rows rh*8 + {0,1,2,3}
        ulonglong2 h1 = hv[1];   // rows rh*8 + {4,5,6,7}
        a0[0] = ffma2(h0.x, w0, a0[0]);
        a0[1] = ffma2(h0.y, w0, a0[1]);
        a0[2] = ffma2(h1.x, w0, a0[2]);
        a0[3] = ffma2(h1.y, w0, a0[3]);
        a1[0] = ffma2(h0.x, w1, a1[0]);
        a1[1] = ffma2(h0.y, w1, a1[1]);
        a1[2] = ffma2(h1.x, w1, a1[2]);
        a1[3] = ffma2(h1.y, w1, a1[3]);
    }
    #pragma unroll
    for (int q = 0; q < 4; ++q) {
        float x0, y0, x1, y1;
        unpack2(a0[q], x0, y0);   // rows rh*8+2q, +2q+1, col 2cc
        unpack2(a1[q], x1, y1);   // same rows, col 2cc+1
        int r0 = rh * 8 + 2 * q, r1 = r0 + 1;
        if (r0 < nb) {
            int poly = g_active[base + r0];
            *(float2*)&pos_out[(size_t)poly * D2 + 2 * cc] = make_float2(x0, x1);
        }
        if (r1 < nb) {
            int poly = g_active[base + r1];
            *(float2*)&pos_out[(size_t)poly * D2 + 2 * cc] = make_float2(y0, y1);
        }
    }
}

extern "C" void kernel_launch(void* const* d_in, const int* in_sizes, int n_in,
                              void* d_out, int out_size) {
    (void)in_sizes; (void)n_in; (void)out_size;

    const float* tgt   = (const float*)d_in[0];
    const int*   label = (const int*)d_in[1];
    const void*  maskp = d_in[2];
    const float* W1  = (const float*)d_in[3];
    const float* b1  = (const float*)d_in[4];
    const float* g1  = (const float*)d_in[5];
    const float* be1 = (const float*)d_in[6];
    const float* m1  = (const float*)d_in[7];
    const float* v1  = (const float*)d_in[8];
    const float* W2  = (const float*)d_in[9];
    const float* b2  = (const float*)d_in[10];
    const float* W3  = (const float*)d_in[11];
    const float* b3  = (const float*)d_in[12];
    const float* g2  = (const float*)d_in[13];
    const float* be2 = (const float*)d_in[14];
    const float* m2  = (const float*)d_in[15];
    const float* v2  = (const float*)d_in[16];
    const float* W4  = (const float*)d_in[17];
    const float* b4  = (const float*)d_in[18];
    const float* temb = (const float*)d_in[19];
    const float* Wp1 = (const float*)d_in[20];
    const float* bp1 = (const float*)d_in[21];
    const float* Wp2 = (const float*)d_in[22];
    const float* bp2 = (const float*)d_in[23];
    const float* pcr = (const float*)d_in[24];

    precompute_w23_kernel<<<33, 256>>>(W2, W3, b2, b3);
    build_active_kernel<<<BN_TOTAL / 256, 256>>>(maskp);
    map_encoder_kernel<<<BN_TOTAL, 128>>>(
        tgt, label, maskp,
        W1, b1, g1, be1, m1, v1,
        W2, b2, W3, g2, be2, m2, v2,
        W4, b4, temb, (float*)d_out);
    pe_a_kernel<<<BN_TOTAL / 16, 256>>>(tgt, Wp1, bp1, pcr);
    pe_b_kernel<<<BN_TOTAL / 16, 256>>>(Wp2, bp2, (float*)d_out);
}

// round 8
// speedup vs baseline: 1.4012x; 1.0280x over previous
#include <cuda_runtime.h>
#include <float.h>

// Problem constants (fixed by the reference: B=16, N=1024, M=21, D=256, V=16)
#define BN_TOTAL (16 * 1024)
#define MPTS 21
#define PP 20      // M-1 points per polyline
#define D1 128
#define D2 256

typedef unsigned long long ull;

// ---- packed f32x2 helpers (Blackwell FFMA2) ----
__device__ __forceinline__ ull pack2(float x, float y) {
    ull r;
    asm("mov.b64 %0, {%1, %2};" : "=l"(r) : "f"(x), "f"(y));
    return r;
}
__device__ __forceinline__ void unpack2(ull v, float& x, float& y) {
    asm("mov.b64 {%0, %1}, %2;" : "=f"(x), "=f"(y) : "l"(v));
}
__device__ __forceinline__ ull ffma2(ull a, ull b, ull c) {
    ull d;
    asm("fma.rn.f32x2 %0, %1, %2, %3;" : "=l"(d) : "l"(a), "l"(b), "l"(c));
    return d;
}

__device__ float g_W23[D1 * D2];   // W2 @ W3[:256]  (128x256)
__device__ float g_bc[D2];         // b2 @ W3[:256] + b3
__device__ float g_scale[D2];      // sine arg multiplier per channel
__device__ int   g_count;
__device__ int   g_active[BN_TOTAL];

// ---- precompute: W23, bc, sine scale table, zero active-count ----
__global__ void precompute_w23_kernel(const float* __restrict__ W2,
                                      const float* __restrict__ W3,
                                      const float* __restrict__ b2,
                                      const float* __restrict__ b3) {
    __shared__ float rows[4][D2];
    const int blk = blockIdx.x;
    const int d = threadIdx.x;   // 0..255
    if (blk < 32) {
        #pragma unroll
        for (int r = 0; r < 4; ++r) rows[r][d] = W2[(4 * blk + r) * D2 + d];
        __syncthreads();
        float a0 = 0.f, a1 = 0.f, a2 = 0.f, a3 = 0.f;
        #pragma unroll 4
        for (int k = 0; k < D2; ++k) {
            float w = W3[k * D2 + d];
            a0 = fmaf(rows[0][k], w, a0);
            a1 = fmaf(rows[1][k], w, a1);
            a2 = fmaf(rows[2][k], w, a2);
            a3 = fmaf(rows[3][k], w, a3);
        }
        g_W23[(4 * blk + 0) * D2 + d] = a0;
        g_W23[(4 * blk + 1) * D2 + d] = a1;
        g_W23[(4 * blk + 2) * D2 + d] = a2;
        g_W23[(4 * blk + 3) * D2 + d] = a3;
    } else {
        rows[0][d] = b2[d];
        __syncthreads();
        float a = 0.f;
        #pragma unroll 4
        for (int k = 0; k < D2; ++k) a = fmaf(rows[0][k], W3[k * D2 + d], a);
        g_bc[d] = a + b3[d];
        // sine scale table: channel d -> 2*pi / 10000^(i/64), i = (d&127)>>1
        int i = (d & 127) >> 1;
        float freq = powf(10000.0f, (float)i * (1.0f / 64.0f));
        g_scale[d] = 6.283185307179586f / freq;
        if (d == 0) g_count = 0;
    }
}

// ---- build compacted active-polyline list ----
__global__ void build_active_kernel(const void* __restrict__ maskp) {
    const int t = threadIdx.x;
    const int i = blockIdx.x * 256 + t;
    int f = 0;
    if (t < 64) {
        unsigned v = ((const unsigned*)maskp)[t];
        f = (v & 0xFFFFFF00u) ? 1 : 0;
    }
    int isbyte = __syncthreads_or(f);
    bool m = isbyte ? (((const unsigned char*)maskp)[i] != 0)
                    : (((const int*)maskp)[i] != 0);
    if (m) {
        int p = atomicAdd(&g_count, 1);
        g_active[p] = i;
    }
}

// ---- main per-polyline kernel (map_feats path only; PE split out) ----
// 128 threads. Thread t owns cols (2t, 2t+1), all 20 points. Stage2 (h1@W2
// for pooled max) and stage3's h-term (h1@W23) are fused over one h1-row read.
__global__ __launch_bounds__(128, 4) void map_encoder_kernel(
    const float* __restrict__ tgt,      // (B,N,21,2)
    const int* __restrict__ label,      // (B,N)
    const void* __restrict__ maskp,     // (B,N) bool or int32
    const float* __restrict__ W1, const float* __restrict__ b1,
    const float* __restrict__ g1, const float* __restrict__ be1,
    const float* __restrict__ m1, const float* __restrict__ v1,
    const float* __restrict__ W2, const float* __restrict__ b2,
    const float* __restrict__ W3,
    const float* __restrict__ g2, const float* __restrict__ be2,
    const float* __restrict__ m2, const float* __restrict__ v2,
    const float* __restrict__ W4, const float* __restrict__ b4,
    const float* __restrict__ temb,     // (16,256)
    float* __restrict__ out)
{
    __shared__ __align__(16) float sm_h1T[D1 * PP];  // 10 KB
    __shared__ __align__(16) float sm_h2T[D2 * PP];  // 20 KB
    __shared__ __align__(16) float sm_vec[D2];       // pooled
    __shared__ float sm_pts[MPTS * 2 + 2];
    __shared__ float sm_feat[PP * 6];

    const int idx = blockIdx.x;
    const int t = threadIdx.x;          // 0..127

    // inline mask-dtype detection (uniform across grid)
    int f = 0;
    if (t < 64) {
        unsigned v = ((const unsigned*)maskp)[t];
        f = (v & 0xFFFFFF00u) ? 1 : 0;
    }
    int isbyte = __syncthreads_or(f);
    bool mask = isbyte ? (((const unsigned char*)maskp)[idx] != 0)
                       : (((const int*)maskp)[idx] != 0);

    float* __restrict__ feats_out = out;
    float* __restrict__ pos_out   = out + (size_t)BN_TOTAL * D2;
    float* __restrict__ mask_out  = out + (size_t)2 * BN_TOTAL * D2;

    if (!mask) {
        *(float2*)&feats_out[(size_t)idx * D2 + 2 * t] = make_float2(0.f, 0.f);
        *(float2*)&pos_out[(size_t)idx * D2 + 2 * t]   = make_float2(0.f, 0.f);
        if (t == 0) mask_out[idx] = 1.0f;
        return;
    }
    if (t == 0) mask_out[idx] = 0.0f;

    // ---- load points ----
    const float* ppin = tgt + (size_t)idx * MPTS * 2;
    if (t < MPTS * 2) sm_pts[t] = ppin[t];
    __syncthreads();

    // ---- feature construction ----
    if (t < PP) {
        int p = t;
        float cx = sm_pts[10 * 2], cy = sm_pts[10 * 2 + 1];
        float x0 = sm_pts[2 * p],     y0 = sm_pts[2 * p + 1];
        float x1 = sm_pts[2 * p + 2], y1 = sm_pts[2 * p + 3];
        float pvx = x1 - x0, pvy = y1 - y0;
        float vn = sqrtf(pvx * pvx + pvy * pvy) + 1.0f + 1e-6f;
        float inv = 1.0f / vn;
        sm_feat[p * 6 + 0] = x0 - cx;
        sm_feat[p * 6 + 1] = y0 - cy;
        sm_feat[p * 6 + 2] = pvx;
        sm_feat[p * 6 + 3] = pvy;
        sm_feat[p * 6 + 4] = pvx * inv;
        sm_feat[p * 6 + 5] = pvy * inv;
    }
    __syncthreads();

    // ---- stage 1: feat(20x6)@W1+b1 -> BN1 -> relu -> sm_h1T ----
    {
        int d = t;
        float w0 = W1[0 * D1 + d], w1 = W1[1 * D1 + d], w2 = W1[2 * D1 + d];
        float w3 = W1[3 * D1 + d], w4 = W1[4 * D1 + d], w5 = W1[5 * D1 + d];
        float s  = g1[d] * rsqrtf(v1[d] + 1e-5f);
        float sh = be1[d] - m1[d] * s + b1[d] * s;
        #pragma unroll
        for (int p = 0; p < PP; ++p) {
            const float* fv = &sm_feat[p * 6];
            float lin = fv[0] * w0 + fv[1] * w1 + fv[2] * w2
                      + fv[3] * w3 + fv[4] * w4 + fv[5] * w5;
            sm_h1T[d * PP + p] = fmaxf(lin * s + sh, 0.0f);
        }
    }
    __syncthreads();

    // ---- FUSED stage2 (h1@W2 -> pooled) + stage3 h-term (h1@W23) ----
    ull a3c0[10], a3c1[10];   // kept live into the stage-3 epilogue
    {
        ull a2c0[10], a2c1[10];
        #pragma unroll
        for (int q = 0; q < 10; ++q) {
            a2c0[q] = 0ull; a2c1[q] = 0ull; a3c0[q] = 0ull; a3c1[q] = 0ull;
        }
        #pragma unroll 2
        for (int c = 0; c < D1; ++c) {
            float2 w2v = *(const float2*)(W2 + c * D2 + 2 * t);
            float2 w3v = *(const float2*)(g_W23 + c * D2 + 2 * t);
            ull w20 = pack2(w2v.x, w2v.x), w21 = pack2(w2v.y, w2v.y);
            ull w30 = pack2(w3v.x, w3v.x), w31 = pack2(w3v.y, w3v.y);
            const ulonglong2* hv = (const ulonglong2*)(sm_h1T + c * PP);
            #pragma unroll
            for (int q = 0; q < 5; ++q) {
                ulonglong2 h = hv[q];
                a2c0[2 * q]     = ffma2(h.x, w20, a2c0[2 * q]);
                a2c0[2 * q + 1] = ffma2(h.y, w20, a2c0[2 * q + 1]);
                a2c1[2 * q]     = ffma2(h.x, w21, a2c1[2 * q]);
                a2c1[2 * q + 1] = ffma2(h.y, w21, a2c1[2 * q + 1]);
                a3c0[2 * q]     = ffma2(h.x, w30, a3c0[2 * q]);
                a3c0[2 * q + 1] = ffma2(h.y, w30, a3c0[2 * q + 1]);
                a3c1[2 * q]     = ffma2(h.x, w31, a3c1[2 * q]);
                a3c1[2 * q + 1] = ffma2(h.y, w31, a3c1[2 * q + 1]);
            }
        }
        float2 bb = *(const float2*)(b2 + 2 * t);
        float mx0 = -FLT_MAX, mx1 = -FLT_MAX;
        #pragma unroll
        for (int q = 0; q < 10; ++q) {
            float a, b;
            unpack2(a2c0[q], a, b); mx0 = fmaxf(mx0, fmaxf(a, b));
            unpack2(a2c1[q], a, b); mx1 = fmaxf(mx1, fmaxf(a, b));
        }
        *(float2*)&sm_vec[2 * t] = make_float2(mx0 + bb.x, mx1 + bb.y);
    }
    __syncthreads();

    // ---- stage 3 epilogue: base = pooled@W3[256:] + bc; BN2+relu -> h2T ----
    {
        ull base = 0ull;
        #pragma unroll 4
        for (int c = 0; c < D2; ++c) {
            ull wb = *(const ull*)(W3 + (size_t)(D2 + c) * D2 + 2 * t);
            float pc = sm_vec[c];
            base = ffma2(wb, pack2(pc, pc), base);
        }
        float bx, by;
        unpack2(base, bx, by);
        float2 bcv = *(const float2*)(g_bc + 2 * t);
        bx += bcv.x; by += bcv.y;

        float2 gg = *(const float2*)(g2  + 2 * t);
        float2 vv = *(const float2*)(v2  + 2 * t);
        float2 mm = *(const float2*)(m2  + 2 * t);
        float2 ee = *(const float2*)(be2 + 2 * t);
        float s0 = gg.x * rsqrtf(vv.x + 1e-5f);
        float s1 = gg.y * rsqrtf(vv.y + 1e-5f);
        float sh0 = ee.x - mm.x * s0;
        float sh1 = ee.y - mm.y * s1;
        float* r0 = sm_h2T + (2 * t) * PP;
        float* r1 = sm_h2T + (2 * t + 1) * PP;
        #pragma unroll
        for (int q = 0; q < 10; ++q) {
            float a, b;
            unpack2(a3c0[q], a, b);
            *(float2*)&r0[2 * q] =
                make_float2(fmaxf((a + bx) * s0 + sh0, 0.0f),
                            fmaxf((b + bx) * s0 + sh0, 0.0f));
            unpack2(a3c1[q], a, b);
            *(float2*)&r1[2 * q] =
                make_float2(fmaxf((a + by) * s1 + sh1, 0.0f),
                            fmaxf((b + by) * s1 + sh1, 0.0f));
        }
    }
    __syncthreads();

    // ---- stage 4: h2(20x256)@W4+b4 -> max_p -> +type_emb -> out ----
    {
        ull acc0[10], acc1[10];
        #pragma unroll
        for (int q = 0; q < 10; ++q) { acc0[q] = 0ull; acc1[q] = 0ull; }
        #pragma unroll 2
        for (int c = 0; c < D2; ++c) {
            float2 w = *(const float2*)(W4 + c * D2 + 2 * t);
            ull w0 = pack2(w.x, w.x);
            ull w1 = pack2(w.y, w.y);
            const ulonglong2* hv = (const ulonglong2*)(sm_h2T + c * PP);
            #pragma unroll
            for (int q = 0; q < 5; ++q) {
                ulonglong2 h = hv[q];
                acc0[2 * q]     = ffma2(h.x, w0, acc0[2 * q]);
                acc0[2 * q + 1] = ffma2(h.y, w0, acc0[2 * q + 1]);
                acc1[2 * q]     = ffma2(h.x, w1, acc1[2 * q]);
                acc1[2 * q + 1] = ffma2(h.y, w1, acc1[2 * q + 1]);
            }
        }
        float2 bb = *(const float2*)(b4 + 2 * t);
        float mx0 = -FLT_MAX, mx1 = -FLT_MAX;
        #pragma unroll
        for (int q = 0; q < 10; ++q) {
            float a, b;
            unpack2(acc0[q], a, b); mx0 = fmaxf(mx0, fmaxf(a, b));
            unpack2(acc1[q], a, b); mx1 = fmaxf(mx1, fmaxf(a, b));
        }
        int lb = label[idx];
        float2 tv = *(const float2*)(temb + (size_t)lb * D2 + 2 * t);
        *(float2*)&feats_out[(size_t)idx * D2 + 2 * t] =
            make_float2(mx0 + bb.x + tv.x, mx1 + bb.y + tv.y);
    }
}

// ---- merged PE kernel: sine -> hp (smem, transposed) -> pe, 16 actives/block ----
__global__ __launch_bounds__(256) void pe_kernel(
    const float* __restrict__ tgt,
    const float* __restrict__ Wp1, const float* __restrict__ bp1,
    const float* __restrict__ Wp2, const float* __restrict__ bp2,
    const float* __restrict__ pcr,
    float* __restrict__ out)
{
    __shared__ __align__(16) float s_sine[D2 * 16];   // [c][r], 16 KB
    __shared__ __align__(16) float s_hp[512 * 16];    // [k][r], 32 KB

    const int base = blockIdx.x * 16;
    int nb = g_count - base;
    if (nb <= 0) return;
    if (nb > 16) nb = 16;
    const int t = threadIdx.x;
    float* __restrict__ pos_out = out + (size_t)BN_TOTAL * D2;

    // ---- sine: thread (r = t&15, cg = t>>4) computes 16 channels for row r ----
    {
        int r = t & 15, cg = t >> 4;
        int rr = (r < nb) ? r : 0;
        int poly = g_active[base + rr];
        float cvx = tgt[(size_t)poly * (MPTS * 2) + 20];
        float cvy = tgt[(size_t)poly * (MPTS * 2) + 21];
        float px = (cvx - pcr[0]) / (pcr[3] - pcr[0]);
        float py = (cvy - pcr[1]) / (pcr[4] - pcr[1]);
        #pragma unroll
        for (int j = 0; j < 16; ++j) {
            int c = cg + 16 * j;
            float pos = (c < 128) ? py : px;
            float arg = pos * g_scale[c];
            s_sine[c * 16 + r] = (c & 1) ? cosf(arg) : sinf(arg);
        }
    }
    __syncthreads();

    // ---- hp = relu(sine @ Wp1 + bp1): thread t -> hp-cols (2t, 2t+1), 16 rows.
    // Results stored TRANSPOSED into s_hp[k][r] (no global round-trip). ----
    {
        ull a0[8], a1[8];
        float2 bb = *(const float2*)(bp1 + 2 * t);
        #pragma unroll
        for (int q = 0; q < 8; ++q) { a0[q] = pack2(bb.x, bb.x); a1[q] = pack2(bb.y, bb.y); }
        #pragma unroll 2
        for (int c = 0; c < D2; ++c) {
            float2 w = *(const float2*)(Wp1 + c * 512 + 2 * t);
            ull w0 = pack2(w.x, w.x), w1 = pack2(w.y, w.y);
            const ulonglong2* sv = (const ulonglong2*)(s_sine + c * 16);
            #pragma unroll
            for (int q = 0; q < 4; ++q) {
                ulonglong2 h = sv[q];
                a0[2 * q]     = ffma2(h.x, w0, a0[2 * q]);
                a0[2 * q + 1] = ffma2(h.y, w0, a0[2 * q + 1]);
                a1[2 * q]     = ffma2(h.x, w1, a1[2 * q]);
                a1[2 * q + 1] = ffma2(h.y, w1, a1[2 * q + 1]);
            }
        }
        float* k0 = s_hp + (2 * t) * 16;       // hp column 2t, rows 0..15
        float* k1 = s_hp + (2 * t + 1) * 16;   // hp column 2t+1
        #pragma unroll
        for (int q = 0; q < 8; ++q) {
            float x, y;
            unpack2(a0[q], x, y);   // rows 2q, 2q+1 of col 2t
            *(float2*)&k0[2 * q] = make_float2(fmaxf(x, 0.f), fmaxf(y, 0.f));
            unpack2(a1[q], x, y);
            *(float2*)&k1[2 * q] = make_float2(fmaxf(x, 0.f), fmaxf(y, 0.f));
        }
    }
    __syncthreads();

    // ---- pe = hp @ Wp2 + bp2: thread (cc = t&127 -> cols 2cc,2cc+1;
    //      rh = t>>7 -> rows rh*8..rh*8+7) ----
    {
        const int cc = t & 127, rh = t >> 7;
        ull a0[4], a1[4];
        float2 bb = *(const float2*)(bp2 + 2 * cc);
        #pragma unroll
        for (int q = 0; q < 4; ++q) { a0[q] = pack2(bb.x, bb.x); a1[q] = pack2(bb.y, bb.y); }
        #pragma unroll 4
        for (int k = 0; k < 512; ++k) {
            float2 w = *(const float2*)(Wp2 + k * D2 + 2 * cc);
            ull w0 = pack2(w.x, w.x), w1 = pack2(w.y, w.y);
            const ulonglong2* hv = (const ulonglong2*)(s_hp + k * 16 + rh * 8);
            ulonglong2 h0 = hv[0];   // rows rh*8 + {0,1,2,3}
            ulonglong2 h1 = hv[1];   // rows rh*8 + {4,5,6,7}
            a0[0] = ffma2(h0.x, w0, a0[0]);
            a0[1] = ffma2(h0.y, w0, a0[1]);
            a0[2] = ffma2(h1.x, w0, a0[2]);
            a0[3] = ffma2(h1.y, w0, a0[3]);
            a1[0] = ffma2(h0.x, w1, a1[0]);
            a1[1] = ffma2(h0.y, w1, a1[1]);
            a1[2] = ffma2(h1.x, w1, a1[2]);
            a1[3] = ffma2(h1.y, w1, a1[3]);
        }
        #pragma unroll
        for (int q = 0; q < 4; ++q) {
            float x0, y0, x1, y1;
            unpack2(a0[q], x0, y0);   // rows rh*8+2q, +2q+1, col 2cc
            unpack2(a1[q], x1, y1);   // same rows, col 2cc+1
            int r0 = rh * 8 + 2 * q, r1 = r0 + 1;
            if (r0 < nb) {
                int poly = g_active[base + r0];
                *(float2*)&pos_out[(size_t)poly * D2 + 2 * cc] = make_float2(x0, x1);
            }
            if (r1 < nb) {
                int poly = g_active[base + r1];
                *(float2*)&pos_out[(size_t)poly * D2 + 2 * cc] = make_float2(y0, y1);
            }
        }
    }
}

extern "C" void kernel_launch(void* const* d_in, const int* in_sizes, int n_in,
                              void* d_out, int out_size) {
    (void)in_sizes; (void)n_in; (void)out_size;

    const float* tgt   = (const float*)d_in[0];
    const int*   label = (const int*)d_in[1];
    const void*  maskp = d_in[2];
    const float* W1  = (const float*)d_in[3];
    const float* b1  = (const float*)d_in[4];
    const float* g1  = (const float*)d_in[5];
    const float* be1 = (const float*)d_in[6];
    const float* m1  = (const float*)d_in[7];
    const float* v1  = (const float*)d_in[8];
    const float* W2  = (const float*)d_in[9];
    const float* b2  = (const float*)d_in[10];
    const float* W3  = (const float*)d_in[11];
    const float* b3  = (const float*)d_in[12];
    const float* g2  = (const float*)d_in[13];
    const float* be2 = (const float*)d_in[14];
    const float* m2  = (const float*)d_in[15];
    const float* v2  = (const float*)d_in[16];
    const float* W4  = (const float*)d_in[17];
    const float* b4  = (const float*)d_in[18];
    const float* temb = (const float*)d_in[19];
    const float* Wp1 = (const float*)d_in[20];
    const float* bp1 = (const float*)d_in[21];
    const float* Wp2 = (const float*)d_in[22];
    const float* bp2 = (const float*)d_in[23];
    const float* pcr = (const float*)d_in[24];

    precompute_w23_kernel<<<33, 256>>>(W2, W3, b2, b3);
    build_active_kernel<<<BN_TOTAL / 256, 256>>>(maskp);
    map_encoder_kernel<<<BN_TOTAL, 128>>>(
        tgt, label, maskp,
        W1, b1, g1, be1, m1, v1,
        W2, b2, W3, g2, be2, m2, v2,
        W4, b4, temb, (float*)d_out);
    pe_kernel<<<BN_TOTAL / 16, 256>>>(tgt, Wp1, bp1, Wp2, bp2, pcr, (float*)d_out);
}

// round 10
// speedup vs baseline: 1.4811x; 1.0570x over previous
#include <cuda_runtime.h>
#include <float.h>

// Problem constants (fixed by the reference: B=16, N=1024, M=21, D=256, V=16)
#define BN_TOTAL (16 * 1024)
#define MPTS 21
#define PP 20      // M-1 points per polyline
#define D1 128
#define D2 256

typedef unsigned long long ull;

// ---- packed f32x2 helpers (Blackwell FFMA2) ----
__device__ __forceinline__ ull pack2(float x, float y) {
    ull r;
    asm("mov.b64 %0, {%1, %2};" : "=l"(r) : "f"(x), "f"(y));
    return r;
}
__device__ __forceinline__ void unpack2(ull v, float& x, float& y) {
    asm("mov.b64 {%0, %1}, %2;" : "=f"(x), "=f"(y) : "l"(v));
}
__device__ __forceinline__ ull ffma2(ull a, ull b, ull c) {
    ull d;
    asm("fma.rn.f32x2 %0, %1, %2, %3;" : "=l"(d) : "l"(a), "l"(b), "l"(c));
    return d;
}

__device__ float g_W23[D1 * D2];   // W2 @ W3[:256]  (128x256)
__device__ float g_bc[D2];         // b2 @ W3[:256] + b3
__device__ float g_scale[D2];      // sine arg multiplier per channel
__device__ int   g_count;
__device__ int   g_active[BN_TOTAL];

// ---- precompute: W23, bc, sine scale table, zero active-count ----
__global__ void precompute_w23_kernel(const float* __restrict__ W2,
                                      const float* __restrict__ W3,
                                      const float* __restrict__ b2,
                                      const float* __restrict__ b3) {
    __shared__ float rows[4][D2];
    const int blk = blockIdx.x;
    const int d = threadIdx.x;   // 0..255
    if (blk < 32) {
        #pragma unroll
        for (int r = 0; r < 4; ++r) rows[r][d] = W2[(4 * blk + r) * D2 + d];
        __syncthreads();
        float a0 = 0.f, a1 = 0.f, a2 = 0.f, a3 = 0.f;
        #pragma unroll 4
        for (int k = 0; k < D2; ++k) {
            float w = W3[k * D2 + d];
            a0 = fmaf(rows[0][k], w, a0);
            a1 = fmaf(rows[1][k], w, a1);
            a2 = fmaf(rows[2][k], w, a2);
            a3 = fmaf(rows[3][k], w, a3);
        }
        g_W23[(4 * blk + 0) * D2 + d] = a0;
        g_W23[(4 * blk + 1) * D2 + d] = a1;
        g_W23[(4 * blk + 2) * D2 + d] = a2;
        g_W23[(4 * blk + 3) * D2 + d] = a3;
    } else {
        rows[0][d] = b2[d];
        __syncthreads();
        float a = 0.f;
        #pragma unroll 4
        for (int k = 0; k < D2; ++k) a = fmaf(rows[0][k], W3[k * D2 + d], a);
        g_bc[d] = a + b3[d];
        int i = (d & 127) >> 1;
        float freq = powf(10000.0f, (float)i * (1.0f / 64.0f));
        g_scale[d] = 6.283185307179586f / freq;
        if (d == 0) g_count = 0;
    }
}

// ---- build compacted active-polyline list ----
__global__ void build_active_kernel(const void* __restrict__ maskp) {
    const int t = threadIdx.x;
    const int i = blockIdx.x * 256 + t;
    int f = 0;
    if (t < 64) {
        unsigned v = ((const unsigned*)maskp)[t];
        f = (v & 0xFFFFFF00u) ? 1 : 0;
    }
    int isbyte = __syncthreads_or(f);
    bool m = isbyte ? (((const unsigned char*)maskp)[i] != 0)
                    : (((const int*)maskp)[i] != 0);
    if (m) {
        int p = atomicAdd(&g_count, 1);
        g_active[p] = i;
    }
}

// ---- shared-memory union: main path vs PE path (max = 48 KB) ----
union SmemU {
    struct {
        float h1T[D1 * PP];         // 10 KB
        float h2T[D2 * PP];         // 20 KB
        float vec[D2];
        float pts[MPTS * 2 + 2];
        float feat[PP * 6];
    } m;
    struct {
        float sine[D2 * 16];        // [c][r]  16 KB
        float hp[512 * 16];         // [k][r]  32 KB
    } p;
};

// ---- merged kernel: grid 17x1024 blocks. bid%17==16 -> PE block (chunk
// bid/17, 16 actives); else main polyline block (poly = bid - bid/17).
// Interleaving keeps each SM's residency ~16:1 main:PE, so PE's fma-dense,
// L1-light work fills the main path's idle fma issue slots.
__global__ __launch_bounds__(128, 4) void map_encoder_kernel(
    const float* __restrict__ tgt,      // (B,N,21,2)
    const int* __restrict__ label,      // (B,N)
    const void* __restrict__ maskp,     // (B,N) bool or int32
    const float* __restrict__ W1, const float* __restrict__ b1,
    const float* __restrict__ g1, const float* __restrict__ be1,
    const float* __restrict__ m1, const float* __restrict__ v1,
    const float* __restrict__ W2, const float* __restrict__ b2,
    const float* __restrict__ W3,
    const float* __restrict__ g2, const float* __restrict__ be2,
    const float* __restrict__ m2, const float* __restrict__ v2,
    const float* __restrict__ W4, const float* __restrict__ b4,
    const float* __restrict__ temb,     // (16,256)
    const float* __restrict__ Wp1, const float* __restrict__ bp1,
    const float* __restrict__ Wp2, const float* __restrict__ bp2,
    const float* __restrict__ pcr,      // (6,)
    float* __restrict__ out)
{
    __shared__ __align__(16) SmemU sm;

    const int bid = blockIdx.x;
    const int t = threadIdx.x;          // 0..127
    const int q17 = bid / 17;
    float* __restrict__ pos_out = out + (size_t)BN_TOTAL * D2;

    if (bid - q17 * 17 == 16) {
        // ================= PE block: chunk q17, 16 active rows =================
        const int base = q17 * 16;
        int nb = g_count - base;
        if (nb <= 0) return;
        if (nb > 16) nb = 16;

        // ---- sine: thread (r=t&15, cg=t>>4) computes channels cg*32..cg*32+31 ----
        {
            int r = t & 15, cg = t >> 4;
            int rr = (r < nb) ? r : 0;
            int poly = g_active[base + rr];
            float cvx = tgt[(size_t)poly * (MPTS * 2) + 20];
            float cvy = tgt[(size_t)poly * (MPTS * 2) + 21];
            float px = (cvx - pcr[0]) / (pcr[3] - pcr[0]);
            float py = (cvy - pcr[1]) / (pcr[4] - pcr[1]);
            float pos = (cg < 4) ? py : px;
            #pragma unroll
            for (int j = 0; j < 32; ++j) {
                int c = cg * 32 + j;
                float arg = pos * g_scale[c];
                sm.p.sine[c * 16 + r] = (c & 1) ? cosf(arg) : sinf(arg);
            }
        }
        __syncthreads();

        // ---- hp = relu(sine @ Wp1 + bp1): thread t -> cols 4t..4t+3, 16 rows ----
        {
            ull a[4][8];
            float4 bb = *(const float4*)(bp1 + 4 * t);
            float bj[4] = {bb.x, bb.y, bb.z, bb.w};
            #pragma unroll
            for (int j = 0; j < 4; ++j)
                #pragma unroll
                for (int q = 0; q < 8; ++q) a[j][q] = pack2(bj[j], bj[j]);
            #pragma unroll 2
            for (int c = 0; c < D2; ++c) {
                float4 w = *(const float4*)(Wp1 + c * 512 + 4 * t);
                ull w0 = pack2(w.x, w.x), w1 = pack2(w.y, w.y);
                ull w2v = pack2(w.z, w.z), w3v = pack2(w.w, w.w);
                const ulonglong2* sv = (const ulonglong2*)(sm.p.sine + c * 16);
                ulonglong2 hA = sv[0], hB = sv[1];
                a[0][0] = ffma2(hA.x, w0, a[0][0]);
                a[0][1] = ffma2(hA.y, w0, a[0][1]);
                a[0][2] = ffma2(hB.x, w0, a[0][2]);
                a[0][3] = ffma2(hB.y, w0, a[0][3]);
                a[1][0] = ffma2(hA.x, w1, a[1][0]);
                a[1][1] = ffma2(hA.y, w1, a[1][1]);
                a[1][2] = ffma2(hB.x, w1, a[1][2]);
                a[1][3] = ffma2(hB.y, w1, a[1][3]);
                a[2][0] = ffma2(hA.x, w2v, a[2][0]);
                a[2][1] = ffma2(hA.y, w2v, a[2][1]);
                a[2][2] = ffma2(hB.x, w2v, a[2][2]);
                a[2][3] = ffma2(hB.y, w2v, a[2][3]);
                a[3][0] = ffma2(hA.x, w3v, a[3][0]);
                a[3][1] = ffma2(hA.y, w3v, a[3][1]);
                a[3][2] = ffma2(hB.x, w3v, a[3][2]);
                a[3][3] = ffma2(hB.y, w3v, a[3][3]);
                ulonglong2 hC = sv[2], hD = sv[3];
                a[0][4] = ffma2(hC.x, w0, a[0][4]);
                a[0][5] = ffma2(hC.y, w0, a[0][5]);
                a[0][6] = ffma2(hD.x, w0, a[0][6]);
                a[0][7] = ffma2(hD.y, w0, a[0][7]);
                a[1][4] = ffma2(hC.x, w1, a[1][4]);
                a[1][5] = ffma2(hC.y, w1, a[1][5]);
                a[1][6] = ffma2(hD.x, w1, a[1][6]);
                a[1][7] = ffma2(hD.y, w1, a[1][7]);
                a[2][4] = ffma2(hC.x, w2v, a[2][4]);
                a[2][5] = ffma2(hC.y, w2v, a[2][5]);
                a[2][6] = ffma2(hD.x, w2v, a[2][6]);
                a[2][7] = ffma2(hD.y, w2v, a[2][7]);
                a[3][4] = ffma2(hC.x, w3v, a[3][4]);
                a[3][5] = ffma2(hC.y, w3v, a[3][5]);
                a[3][6] = ffma2(hD.x, w3v, a[3][6]);
                a[3][7] = ffma2(hD.y, w3v, a[3][7]);
            }
            __syncthreads();   // all sine reads complete before hp stores
            #pragma unroll
            for (int j = 0; j < 4; ++j) {
                float* kcol = sm.p.hp + (4 * t + j) * 16;
                #pragma unroll
                for (int q = 0; q < 8; ++q) {
                    float x, y;
                    unpack2(a[j][q], x, y);
                    *(float2*)&kcol[2 * q] =
                        make_float2(fmaxf(x, 0.f), fmaxf(y, 0.f));
                }
            }
        }
        __syncthreads();

        // ---- pe = hp @ Wp2 + bp2: thread t -> cols 2t, 2t+1, 16 rows ----
        {
            ull a0[8], a1[8];
            float2 bb = *(const float2*)(bp2 + 2 * t);
            #pragma unroll
            for (int q = 0; q < 8; ++q) {
                a0[q] = pack2(bb.x, bb.x);
                a1[q] = pack2(bb.y, bb.y);
            }
            #pragma unroll 2
            for (int k = 0; k < 512; ++k) {
                float2 w = *(const float2*)(Wp2 + k * D2 + 2 * t);
                ull w0 = pack2(w.x, w.x), w1 = pack2(w.y, w.y);
                const ulonglong2* hv = (const ulonglong2*)(sm.p.hp + k * 16);
                ulonglong2 hA = hv[0], hB = hv[1];
                a0[0] = ffma2(hA.x, w0, a0[0]);
                a0[1] = ffma2(hA.y, w0, a0[1]);
                a0[2] = ffma2(hB.x, w0, a0[2]);
                a0[3] = ffma2(hB.y, w0, a0[3]);
                a1[0] = ffma2(hA.x, w1, a1[0]);
                a1[1] = ffma2(hA.y, w1, a1[1]);
                a1[2] = ffma2(hB.x, w1, a1[2]);
                a1[3] = ffma2(hB.y, w1, a1[3]);
                ulonglong2 hC = hv[2], hD = hv[3];
                a0[4] = ffma2(hC.x, w0, a0[4]);
                a0[5] = ffma2(hC.y, w0, a0[5]);
                a0[6] = ffma2(hD.x, w0, a0[6]);
                a0[7] = ffma2(hD.y, w0, a0[7]);
                a1[4] = ffma2(hC.x, w1, a1[4]);
                a1[5] = ffma2(hC.y, w1, a1[5]);
                a1[6] = ffma2(hD.x, w1, a1[6]);
                a1[7] = ffma2(hD.y, w1, a1[7]);
            }
            #pragma unroll
            for (int q = 0; q < 8; ++q) {
                float x0, y0, x1, y1;
                unpack2(a0[q], x0, y0);   // rows 2q, 2q+1 of col 2t
                unpack2(a1[q], x1, y1);   // rows 2q, 2q+1 of col 2t+1
                int r0 = 2 * q, r1 = 2 * q + 1;
                if (r0 < nb) {
                    int poly = g_active[base + r0];
                    *(float2*)&pos_out[(size_t)poly * D2 + 2 * t] =
                        make_float2(x0, x1);
                }
                if (r1 < nb) {
                    int poly = g_active[base + r1];
                    *(float2*)&pos_out[(size_t)poly * D2 + 2 * t] =
                        make_float2(y0, y1);
                }
            }
        }
        return;
    }

    // ===================== main polyline block =====================
    const int idx = bid - q17;

    // inline mask-dtype detection (uniform across grid)
    int f = 0;
    if (t < 64) {
        unsigned v = ((const unsigned*)maskp)[t];
        f = (v & 0xFFFFFF00u) ? 1 : 0;
    }
    int isbyte = __syncthreads_or(f);
    bool mask = isbyte ? (((const unsigned char*)maskp)[idx] != 0)
                       : (((const int*)maskp)[idx] != 0);

    float* __restrict__ feats_out = out;
    float* __restrict__ mask_out  = out + (size_t)2 * BN_TOTAL * D2;

    if (!mask) {
        *(float2*)&feats_out[(size_t)idx * D2 + 2 * t] = make_float2(0.f, 0.f);
        *(float2*)&pos_out[(size_t)idx * D2 + 2 * t]   = make_float2(0.f, 0.f);
        if (t == 0) mask_out[idx] = 1.0f;
        return;
    }
    if (t == 0) mask_out[idx] = 0.0f;

    // ---- load points ----
    const float* ppin = tgt + (size_t)idx * MPTS * 2;
    if (t < MPTS * 2) sm.m.pts[t] = ppin[t];
    __syncthreads();

    // ---- feature construction ----
    if (t < PP) {
        int p = t;
        float cx = sm.m.pts[10 * 2], cy = sm.m.pts[10 * 2 + 1];
        float x0 = sm.m.pts[2 * p],     y0 = sm.m.pts[2 * p + 1];
        float x1 = sm.m.pts[2 * p + 2], y1 = sm.m.pts[2 * p + 3];
        float pvx = x1 - x0, pvy = y1 - y0;
        float vn = sqrtf(pvx * pvx + pvy * pvy) + 1.0f + 1e-6f;
        float inv = 1.0f / vn;
        sm.m.feat[p * 6 + 0] = x0 - cx;
        sm.m.feat[p * 6 + 1] = y0 - cy;
        sm.m.feat[p * 6 + 2] = pvx;
        sm.m.feat[p * 6 + 3] = pvy;
        sm.m.feat[p * 6 + 4] = pvx * inv;
        sm.m.feat[p * 6 + 5] = pvy * inv;
    }
    __syncthreads();

    // ---- stage 1: feat(20x6)@W1+b1 -> BN1 -> relu -> h1T ----
    {
        int d = t;
        float w0 = W1[0 * D1 + d], w1 = W1[1 * D1 + d], w2 = W1[2 * D1 + d];
        float w3 = W1[3 * D1 + d], w4 = W1[4 * D1 + d], w5 = W1[5 * D1 + d];
        float s  = g1[d] * rsqrtf(v1[d] + 1e-5f);
        float sh = be1[d] - m1[d] * s + b1[d] * s;
        #pragma unroll
        for (int p = 0; p < PP; ++p) {
            const float* fv = &sm.m.feat[p * 6];
            float lin = fv[0] * w0 + fv[1] * w1 + fv[2] * w2
                      + fv[3] * w3 + fv[4] * w4 + fv[5] * w5;
            sm.m.h1T[d * PP + p] = fmaxf(lin * s + sh, 0.0f);
        }
    }
    __syncthreads();

    // ---- FUSED stage2 (h1@W2 -> pooled) + stage3 h-term (h1@W23) ----
    ull a3c0[10], a3c1[10];
    {
        ull a2c0[10], a2c1[10];
        #pragma unroll
        for (int q = 0; q < 10; ++q) {
            a2c0[q] = 0ull; a2c1[q] = 0ull; a3c0[q] = 0ull; a3c1[q] = 0ull;
        }
        #pragma unroll 2
        for (int c = 0; c < D1; ++c) {
            float2 w2v = *(const float2*)(W2 + c * D2 + 2 * t);
            float2 w3v = *(const float2*)(g_W23 + c * D2 + 2 * t);
            ull w20 = pack2(w2v.x, w2v.x), w21 = pack2(w2v.y, w2v.y);
            ull w30 = pack2(w3v.x, w3v.x), w31 = pack2(w3v.y, w3v.y);
            const ulonglong2* hv = (const ulonglong2*)(sm.m.h1T + c * PP);
            #pragma unroll
            for (int q = 0; q < 5; ++q) {
                ulonglong2 h = hv[q];
                a2c0[2 * q]     = ffma2(h.x, w20, a2c0[2 * q]);
                a2c0[2 * q + 1] = ffma2(h.y, w20, a2c0[2 * q + 1]);
                a2c1[2 * q]     = ffma2(h.x, w21, a2c1[2 * q]);
                a2c1[2 * q + 1] = ffma2(h.y, w21, a2c1[2 * q + 1]);
                a3c0[2 * q]     = ffma2(h.x, w30, a3c0[2 * q]);
                a3c0[2 * q + 1] = ffma2(h.y, w30, a3c0[2 * q + 1]);
                a3c1[2 * q]     = ffma2(h.x, w31, a3c1[2 * q]);
                a3c1[2 * q + 1] = ffma2(h.y, w31, a3c1[2 * q + 1]);
            }
        }
        float2 bb = *(const float2*)(b2 + 2 * t);
        float mx0 = -FLT_MAX, mx1 = -FLT_MAX;
        #pragma unroll
        for (int q = 0; q < 10; ++q) {
            float a, b;
            unpack2(a2c0[q], a, b); mx0 = fmaxf(mx0, fmaxf(a, b));
            unpack2(a2c1[q], a, b); mx1 = fmaxf(mx1, fmaxf(a, b));
        }
        *(float2*)&sm.m.vec[2 * t] = make_float2(mx0 + bb.x, mx1 + bb.y);
    }
    __syncthreads();

    // ---- stage 3 epilogue: base = pooled@W3[256:] + bc; BN2+relu -> h2T ----
    {
        ull base = 0ull;
        #pragma unroll 4
        for (int c = 0; c < D2; ++c) {
            ull wb = *(const ull*)(W3 + (size_t)(D2 + c) * D2 + 2 * t);
            float pc = sm.m.vec[c];
            base = ffma2(wb, pack2(pc, pc), base);
        }
        float bx, by;
        unpack2(base, bx, by);
        float2 bcv = *(const float2*)(g_bc + 2 * t);
        bx += bcv.x; by += bcv.y;

        float2 gg = *(const float2*)(g2  + 2 * t);
        float2 vv = *(const float2*)(v2  + 2 * t);
        float2 mm = *(const float2*)(m2  + 2 * t);
        float2 ee = *(const float2*)(be2 + 2 * t);
        float s0 = gg.x * rsqrtf(vv.x + 1e-5f);
        float s1 = gg.y * rsqrtf(vv.y + 1e-5f);
        float sh0 = ee.x - mm.x * s0;
        float sh1 = ee.y - mm.y * s1;
        float* r0 = sm.m.h2T + (2 * t) * PP;
        float* r1 = sm.m.h2T + (2 * t + 1) * PP;
        #pragma unroll
        for (int q = 0; q < 10; ++q) {
            float a, b;
            unpack2(a3c0[q], a, b);
            *(float2*)&r0[2 * q] =
                make_float2(fmaxf((a + bx) * s0 + sh0, 0.0f),
                            fmaxf((b + bx) * s0 + sh0, 0.0f));
            unpack2(a3c1[q], a, b);
            *(float2*)&r1[2 * q] =
                make_float2(fmaxf((a + by) * s1 + sh1, 0.0f),
                            fmaxf((b + by) * s1 + sh1, 0.0f));
        }
    }
    __syncthreads();

    // ---- stage 4: h2(20x256)@W4+b4 -> max_p -> +type_emb -> out ----
    {
        ull acc0[10], acc1[10];
        #pragma unroll
        for (int q = 0; q < 10; ++q) { acc0[q] = 0ull; acc1[q] = 0ull; }
        #pragma unroll 2
        for (int c = 0; c < D2; ++c) {
            float2 w = *(const float2*)(W4 + c * D2 + 2 * t);
            ull w0 = pack2(w.x, w.x);
            ull w1 = pack2(w.y, w.y);
            const ulonglong2* hv = (const ulonglong2*)(sm.m.h2T + c * PP);
            #pragma unroll
            for (int q = 0; q < 5; ++q) {
                ulonglong2 h = hv[q];
                acc0[2 * q]     = ffma2(h.x, w0, acc0[2 * q]);
                acc0[2 * q + 1] = ffma2(h.y, w0, acc0[2 * q + 1]);
                acc1[2 * q]     = ffma2(h.x, w1, acc1[2 * q]);
                acc1[2 * q + 1] = ffma2(h.y, w1, acc1[2 * q + 1]);
            }
        }
        float2 bb = *(const float2*)(b4 + 2 * t);
        float mx0 = -FLT_MAX, mx1 = -FLT_MAX;
        #pragma unroll
        for (int q = 0; q < 10; ++q) {
            float a, b;
            unpack2(acc0[q], a, b); mx0 = fmaxf(mx0, fmaxf(a, b));
            unpack2(acc1[q], a, b); mx1 = fmaxf(mx1, fmaxf(a, b));
        }
        int lb = label[idx];
        float2 tv = *(const float2*)(temb + (size_t)lb * D2 + 2 * t);
        *(float2*)&feats_out[(size_t)idx * D2 + 2 * t] =
            make_float2(mx0 + bb.x + tv.x, mx1 + bb.y + tv.y);
    }
}

extern "C" void kernel_launch(void* const* d_in, const int* in_sizes, int n_in,
                              void* d_out, int out_size) {
    (void)in_sizes; (void)n_in; (void)out_size;

    const float* tgt   = (const float*)d_in[0];
    const int*   label = (const int*)d_in[1];
    const void*  maskp = d_in[2];
    const float* W1  = (const float*)d_in[3];
    const float* b1  = (const float*)d_in[4];
    const float* g1  = (const float*)d_in[5];
    const float* be1 = (const float*)d_in[6];
    const float* m1  = (const float*)d_in[7];
    const float* v1  = (const float*)d_in[8];
    const float* W2  = (const float*)d_in[9];
    const float* b2  = (const float*)d_in[10];
    const float* W3  = (const float*)d_in[11];
    const float* b3  = (const float*)d_in[12];
    const float* g2  = (const float*)d_in[13];
    const float* be2 = (const float*)d_in[14];
    const float* m2  = (const float*)d_in[15];
    const float* v2  = (const float*)d_in[16];
    const float* W4  = (const float*)d_in[17];
    const float* b4  = (const float*)d_in[18];
    const float* temb = (const float*)d_in[19];
    const float* Wp1 = (const float*)d_in[20];
    const float* bp1 = (const float*)d_in[21];
    const float* Wp2 = (const float*)d_in[22];
    const float* bp2 = (const float*)d_in[23];
    const float* pcr = (const float*)d_in[24];

    precompute_w23_kernel<<<33, 256>>>(W2, W3, b2, b3);
    build_active_kernel<<<BN_TOTAL / 256, 256>>>(maskp);
    map_encoder_kernel<<<17 * (BN_TOTAL / 16), 128>>>(
        tgt, label, maskp,
        W1, b1, g1, be1, m1, v1,
        W2, b2, W3, g2, be2, m2, v2,
        W4, b4, temb, Wp1, bp1, Wp2, bp2, pcr,
        (float*)d_out);
}

// round 11
// speedup vs baseline: 1.4924x; 1.0076x over previous
#include <cuda_runtime.h>
#include <float.h>

// Problem constants (fixed by the reference: B=16, N=1024, M=21, D=256, V=16)
#define BN_TOTAL (16 * 1024)
#define MPTS 21
#define PP 20      // M-1 points per polyline
#define D1 128
#define D2 256

typedef unsigned long long ull;

// ---- packed f32x2 helpers (Blackwell FFMA2) ----
__device__ __forceinline__ ull pack2(float x, float y) {
    ull r;
    asm("mov.b64 %0, {%1, %2};" : "=l"(r) : "f"(x), "f"(y));
    return r;
}
__device__ __forceinline__ void unpack2(ull v, float& x, float& y) {
    asm("mov.b64 {%0, %1}, %2;" : "=f"(x), "=f"(y) : "l"(v));
}
__device__ __forceinline__ ull ffma2(ull a, ull b, ull c) {
    ull d;
    asm("fma.rn.f32x2 %0, %1, %2, %3;" : "=l"(d) : "l"(a), "l"(b), "l"(c));
    return d;
}

__device__ float g_W23[D1 * D2];   // W2 @ W3[:256]  (128x256)
__device__ float g_bc[D2];         // b2 @ W3[:256] + b3
__device__ float g_scale[D2];      // sine arg multiplier per channel
__device__ int   g_count;
__device__ int   g_active[BN_TOTAL];

// ---- precompute: W23, bc, sine scale table, zero active-count ----
// Grid 129: blocks 0..127 -> one W23 row each (8-way-MLP inner loop);
// block 128 -> bc + scale table + count reset.
__global__ void precompute_w23_kernel(const float* __restrict__ W2,
                                      const float* __restrict__ W3,
                                      const float* __restrict__ b2,
                                      const float* __restrict__ b3) {
    __shared__ float row[D2];
    const int blk = blockIdx.x;
    const int d = threadIdx.x;   // 0..255
    if (blk < 128) {
        row[d] = W2[blk * D2 + d];     // W2 row `blk`
        __syncthreads();
        float acc[8];
        #pragma unroll
        for (int j = 0; j < 8; ++j) acc[j] = 0.f;
        #pragma unroll 1
        for (int k0 = 0; k0 < D2; k0 += 8) {
            #pragma unroll
            for (int j = 0; j < 8; ++j)
                acc[j] = fmaf(row[k0 + j], W3[(k0 + j) * D2 + d], acc[j]);
        }
        float s = ((acc[0] + acc[1]) + (acc[2] + acc[3]))
                + ((acc[4] + acc[5]) + (acc[6] + acc[7]));
        g_W23[blk * D2 + d] = s;
    } else {
        row[d] = b2[d];
        __syncthreads();
        float acc[8];
        #pragma unroll
        for (int j = 0; j < 8; ++j) acc[j] = 0.f;
        #pragma unroll 1
        for (int k0 = 0; k0 < D2; k0 += 8) {
            #pragma unroll
            for (int j = 0; j < 8; ++j)
                acc[j] = fmaf(row[k0 + j], W3[(k0 + j) * D2 + d], acc[j]);
        }
        float s = ((acc[0] + acc[1]) + (acc[2] + acc[3]))
                + ((acc[4] + acc[5]) + (acc[6] + acc[7]));
        g_bc[d] = s + b3[d];
        int i = (d & 127) >> 1;
        float freq = powf(10000.0f, (float)i * (1.0f / 64.0f));
        g_scale[d] = 6.283185307179586f / freq;
        if (d == 0) g_count = 0;
    }
}

// ---- build compacted active-polyline list ----
__global__ void build_active_kernel(const void* __restrict__ maskp) {
    const int t = threadIdx.x;
    const int i = blockIdx.x * 256 + t;
    int f = 0;
    if (t < 64) {
        unsigned v = ((const unsigned*)maskp)[t];
        f = (v & 0xFFFFFF00u) ? 1 : 0;
    }
    int isbyte = __syncthreads_or(f);
    bool m = isbyte ? (((const unsigned char*)maskp)[i] != 0)
                    : (((const int*)maskp)[i] != 0);
    if (m) {
        int p = atomicAdd(&g_count, 1);
        g_active[p] = i;
    }
}

// ---- shared-memory union: main path vs PE path (max = 48 KB) ----
union SmemU {
    struct {
        float h1T[D1 * PP];         // 10 KB
        float h2T[D2 * PP];         // 20 KB
        float vec[D2];
        float pts[MPTS * 2 + 2];
        float feat[PP * 6];
    } m;
    struct {
        float sine[D2 * 16];        // [c][r]  16 KB
        float hp[512 * 16];         // [k][r]  32 KB
    } p;
};

// ---- merged kernel: grid 17x1024 blocks. bid%17==16 -> PE block (chunk
// bid/17, 16 actives); else main polyline block (poly = bid - bid/17).
// Interleaving keeps each SM's residency ~16:1 main:PE, so PE's fma-dense,
// L1-light work fills the main path's idle fma issue slots.
__global__ __launch_bounds__(128, 4) void map_encoder_kernel(
    const float* __restrict__ tgt,      // (B,N,21,2)
    const int* __restrict__ label,      // (B,N)
    const void* __restrict__ maskp,     // (B,N) bool or int32
    const float* __restrict__ W1, const float* __restrict__ b1,
    const float* __restrict__ g1, const float* __restrict__ be1,
    const float* __restrict__ m1, const float* __restrict__ v1,
    const float* __restrict__ W2, const float* __restrict__ b2,
    const float* __restrict__ W3,
    const float* __restrict__ g2, const float* __restrict__ be2,
    const float* __restrict__ m2, const float* __restrict__ v2,
    const float* __restrict__ W4, const float* __restrict__ b4,
    const float* __restrict__ temb,     // (16,256)
    const float* __restrict__ Wp1, const float* __restrict__ bp1,
    const float* __restrict__ Wp2, const float* __restrict__ bp2,
    const float* __restrict__ pcr,      // (6,)
    float* __restrict__ out)
{
    __shared__ __align__(16) SmemU sm;

    const int bid = blockIdx.x;
    const int t = threadIdx.x;          // 0..127
    const int q17 = bid / 17;
    float* __restrict__ pos_out = out + (size_t)BN_TOTAL * D2;

    if (bid - q17 * 17 == 16) {
        // ================= PE block: chunk q17, 16 active rows =================
        const int base = q17 * 16;
        int nb = g_count - base;
        if (nb <= 0) return;
        if (nb > 16) nb = 16;

        // ---- sine: thread (r=t&15, cg=t>>4) computes channels cg*32..cg*32+31 ----
        {
            int r = t & 15, cg = t >> 4;
            int rr = (r < nb) ? r : 0;
            int poly = g_active[base + rr];
            float cvx = tgt[(size_t)poly * (MPTS * 2) + 20];
            float cvy = tgt[(size_t)poly * (MPTS * 2) + 21];
            float px = (cvx - pcr[0]) / (pcr[3] - pcr[0]);
            float py = (cvy - pcr[1]) / (pcr[4] - pcr[1]);
            float pos = (cg < 4) ? py : px;
            #pragma unroll
            for (int j = 0; j < 32; ++j) {
                int c = cg * 32 + j;
                float arg = pos * g_scale[c];
                sm.p.sine[c * 16 + r] = (c & 1) ? cosf(arg) : sinf(arg);
            }
        }
        __syncthreads();

        // ---- hp = relu(sine @ Wp1 + bp1): thread t -> cols 4t..4t+3, 16 rows ----
        {
            ull a[4][8];
            float4 bb = *(const float4*)(bp1 + 4 * t);
            float bj[4] = {bb.x, bb.y, bb.z, bb.w};
            #pragma unroll
            for (int j = 0; j < 4; ++j)
                #pragma unroll
                for (int q = 0; q < 8; ++q) a[j][q] = pack2(bj[j], bj[j]);
            #pragma unroll 2
            for (int c = 0; c < D2; ++c) {
                float4 w = *(const float4*)(Wp1 + c * 512 + 4 * t);
                ull w0 = pack2(w.x, w.x), w1 = pack2(w.y, w.y);
                ull w2v = pack2(w.z, w.z), w3v = pack2(w.w, w.w);
                const ulonglong2* sv = (const ulonglong2*)(sm.p.sine + c * 16);
                ulonglong2 hA = sv[0], hB = sv[1];
                a[0][0] = ffma2(hA.x, w0, a[0][0]);
                a[0][1] = ffma2(hA.y, w0, a[0][1]);
                a[0][2] = ffma2(hB.x, w0, a[0][2]);
                a[0][3] = ffma2(hB.y, w0, a[0][3]);
                a[1][0] = ffma2(hA.x, w1, a[1][0]);
                a[1][1] = ffma2(hA.y, w1, a[1][1]);
                a[1][2] = ffma2(hB.x, w1, a[1][2]);
                a[1][3] = ffma2(hB.y, w1, a[1][3]);
                a[2][0] = ffma2(hA.x, w2v, a[2][0]);
                a[2][1] = ffma2(hA.y, w2v, a[2][1]);
                a[2][2] = ffma2(hB.x, w2v, a[2][2]);
                a[2][3] = ffma2(hB.y, w2v, a[2][3]);
                a[3][0] = ffma2(hA.x, w3v, a[3][0]);
                a[3][1] = ffma2(hA.y, w3v, a[3][1]);
                a[3][2] = ffma2(hB.x, w3v, a[3][2]);
                a[3][3] = ffma2(hB.y, w3v, a[3][3]);
                ulonglong2 hC = sv[2], hD = sv[3];
                a[0][4] = ffma2(hC.x, w0, a[0][4]);
                a[0][5] = ffma2(hC.y, w0, a[0][5]);
                a[0][6] = ffma2(hD.x, w0, a[0][6]);
                a[0][7] = ffma2(hD.y, w0, a[0][7]);
                a[1][4] = ffma2(hC.x, w1, a[1][4]);
                a[1][5] = ffma2(hC.y, w1, a[1][5]);
                a[1][6] = ffma2(hD.x, w1, a[1][6]);
                a[1][7] = ffma2(hD.y, w1, a[1][7]);
                a[2][4] = ffma2(hC.x, w2v, a[2][4]);
                a[2][5] = ffma2(hC.y, w2v, a[2][5]);
                a[2][6] = ffma2(hD.x, w2v, a[2][6]);
                a[2][7] = ffma2(hD.y, w2v, a[2][7]);
                a[3][4] = ffma2(hC.x, w3v, a[3][4]);
                a[3][5] = ffma2(hC.y, w3v, a[3][5]);
                a[3][6] = ffma2(hD.x, w3v, a[3][6]);
                a[3][7] = ffma2(hD.y, w3v, a[3][7]);
            }
            __syncthreads();   // all sine reads complete before hp stores
            #pragma unroll
            for (int j = 0; j < 4; ++j) {
                float* kcol = sm.p.hp + (4 * t + j) * 16;
                #pragma unroll
                for (int q = 0; q < 8; ++q) {
                    float x, y;
                    unpack2(a[j][q], x, y);
                    *(float2*)&kcol[2 * q] =
                        make_float2(fmaxf(x, 0.f), fmaxf(y, 0.f));
                }
            }
        }
        __syncthreads();

        // ---- pe = hp @ Wp2 + bp2: thread t -> cols 2t, 2t+1, 16 rows ----
        {
            ull a0[8], a1[8];
            float2 bb = *(const float2*)(bp2 + 2 * t);
            #pragma unroll
            for (int q = 0; q < 8; ++q) {
                a0[q] = pack2(bb.x, bb.x);
                a1[q] = pack2(bb.y, bb.y);
            }
            #pragma unroll 2
            for (int k = 0; k < 512; ++k) {
                float2 w = *(const float2*)(Wp2 + k * D2 + 2 * t);
                ull w0 = pack2(w.x, w.x), w1 = pack2(w.y, w.y);
                const ulonglong2* hv = (const ulonglong2*)(sm.p.hp + k * 16);
                ulonglong2 hA = hv[0], hB = hv[1];
                a0[0] = ffma2(hA.x, w0, a0[0]);
                a0[1] = ffma2(hA.y, w0, a0[1]);
                a0[2] = ffma2(hB.x, w0, a0[2]);
                a0[3] = ffma2(hB.y, w0, a0[3]);
                a1[0] = ffma2(hA.x, w1, a1[0]);
                a1[1] = ffma2(hA.y, w1, a1[1]);
                a1[2] = ffma2(hB.x, w1, a1[2]);
                a1[3] = ffma2(hB.y, w1, a1[3]);
                ulonglong2 hC = hv[2], hD = hv[3];
                a0[4] = ffma2(hC.x, w0, a0[4]);
                a0[5] = ffma2(hC.y, w0, a0[5]);
                a0[6] = ffma2(hD.x, w0, a0[6]);
                a0[7] = ffma2(hD.y, w0, a0[7]);
                a1[4] = ffma2(hC.x, w1, a1[4]);
                a1[5] = ffma2(hC.y, w1, a1[5]);
                a1[6] = ffma2(hD.x, w1, a1[6]);
                a1[7] = ffma2(hD.y, w1, a1[7]);
            }
            #pragma unroll
            for (int q = 0; q < 8; ++q) {
                float x0, y0, x1, y1;
                unpack2(a0[q], x0, y0);   // rows 2q, 2q+1 of col 2t
                unpack2(a1[q], x1, y1);   // rows 2q, 2q+1 of col 2t+1
                int r0 = 2 * q, r1 = 2 * q + 1;
                if (r0 < nb) {
                    int poly = g_active[base + r0];
                    *(float2*)&pos_out[(size_t)poly * D2 + 2 * t] =
                        make_float2(x0, x1);
                }
                if (r1 < nb) {
                    int poly = g_active[base + r1];
                    *(float2*)&pos_out[(size_t)poly * D2 + 2 * t] =
                        make_float2(y0, y1);
                }
            }
        }
        return;
    }

    // ===================== main polyline block =====================
    const int idx = bid - q17;

    // inline mask-dtype detection (uniform across grid)
    int f = 0;
    if (t < 64) {
        unsigned v = ((const unsigned*)maskp)[t];
        f = (v & 0xFFFFFF00u) ? 1 : 0;
    }
    int isbyte = __syncthreads_or(f);
    bool mask = isbyte ? (((const unsigned char*)maskp)[idx] != 0)
                       : (((const int*)maskp)[idx] != 0);

    float* __restrict__ feats_out = out;
    float* __restrict__ mask_out  = out + (size_t)2 * BN_TOTAL * D2;

    if (!mask) {
        *(float2*)&feats_out[(size_t)idx * D2 + 2 * t] = make_float2(0.f, 0.f);
        *(float2*)&pos_out[(size_t)idx * D2 + 2 * t]   = make_float2(0.f, 0.f);
        if (t == 0) mask_out[idx] = 1.0f;
        return;
    }
    if (t == 0) mask_out[idx] = 0.0f;

    // ---- load points ----
    const float* ppin = tgt + (size_t)idx * MPTS * 2;
    if (t < MPTS * 2) sm.m.pts[t] = ppin[t];
    __syncthreads();

    // ---- feature construction ----
    if (t < PP) {
        int p = t;
        float cx = sm.m.pts[10 * 2], cy = sm.m.pts[10 * 2 + 1];
        float x0 = sm.m.pts[2 * p],     y0 = sm.m.pts[2 * p + 1];
        float x1 = sm.m.pts[2 * p + 2], y1 = sm.m.pts[2 * p + 3];
        float pvx = x1 - x0, pvy = y1 - y0;
        float vn = sqrtf(pvx * pvx + pvy * pvy) + 1.0f + 1e-6f;
        float inv = 1.0f / vn;
        sm.m.feat[p * 6 + 0] = x0 - cx;
        sm.m.feat[p * 6 + 1] = y0 - cy;
        sm.m.feat[p * 6 + 2] = pvx;
        sm.m.feat[p * 6 + 3] = pvy;
        sm.m.feat[p * 6 + 4] = pvx * inv;
        sm.m.feat[p * 6 + 5] = pvy * inv;
    }
    __syncthreads();

    // ---- stage 1: feat(20x6)@W1+b1 -> BN1 -> relu -> h1T ----
    {
        int d = t;
        float w0 = W1[0 * D1 + d], w1 = W1[1 * D1 + d], w2 = W1[2 * D1 + d];
        float w3 = W1[3 * D1 + d], w4 = W1[4 * D1 + d], w5 = W1[5 * D1 + d];
        float s  = g1[d] * rsqrtf(v1[d] + 1e-5f);
        float sh = be1[d] - m1[d] * s + b1[d] * s;
        #pragma unroll
        for (int p = 0; p < PP; ++p) {
            const float* fv = &sm.m.feat[p * 6];
            float lin = fv[0] * w0 + fv[1] * w1 + fv[2] * w2
                      + fv[3] * w3 + fv[4] * w4 + fv[5] * w5;
            sm.m.h1T[d * PP + p] = fmaxf(lin * s + sh, 0.0f);
        }
    }
    __syncthreads();

    // ---- FUSED stage2 (h1@W2 -> pooled) + stage3 h-term (h1@W23) ----
    ull a3c0[10], a3c1[10];
    {
        ull a2c0[10], a2c1[10];
        #pragma unroll
        for (int q = 0; q < 10; ++q) {
            a2c0[q] = 0ull; a2c1[q] = 0ull; a3c0[q] = 0ull; a3c1[q] = 0ull;
        }
        #pragma unroll 2
        for (int c = 0; c < D1; ++c) {
            float2 w2v = *(const float2*)(W2 + c * D2 + 2 * t);
            float2 w3v = *(const float2*)(g_W23 + c * D2 + 2 * t);
            ull w20 = pack2(w2v.x, w2v.x), w21 = pack2(w2v.y, w2v.y);
            ull w30 = pack2(w3v.x, w3v.x), w31 = pack2(w3v.y, w3v.y);
            const ulonglong2* hv = (const ulonglong2*)(sm.m.h1T + c * PP);
            #pragma unroll
            for (int q = 0; q < 5; ++q) {
                ulonglong2 h = hv[q];
                a2c0[2 * q]     = ffma2(h.x, w20, a2c0[2 * q]);
                a2c0[2 * q + 1] = ffma2(h.y, w20, a2c0[2 * q + 1]);
                a2c1[2 * q]     = ffma2(h.x, w21, a2c1[2 * q]);
                a2c1[2 * q + 1] = ffma2(h.y, w21, a2c1[2 * q + 1]);
                a3c0[2 * q]     = ffma2(h.x, w30, a3c0[2 * q]);
                a3c0[2 * q + 1] = ffma2(h.y, w30, a3c0[2 * q + 1]);
                a3c1[2 * q]     = ffma2(h.x, w31, a3c1[2 * q]);
                a3c1[2 * q + 1] = ffma2(h.y, w31, a3c1[2 * q + 1]);
            }
        }
        float2 bb = *(const float2*)(b2 + 2 * t);
        float mx0 = -FLT_MAX, mx1 = -FLT_MAX;
        #pragma unroll
        for (int q = 0; q < 10; ++q) {
            float a, b;
            unpack2(a2c0[q], a, b); mx0 = fmaxf(mx0, fmaxf(a, b));
            unpack2(a2c1[q], a, b); mx1 = fmaxf(mx1, fmaxf(a, b));
        }
        *(float2*)&sm.m.vec[2 * t] = make_float2(mx0 + bb.x, mx1 + bb.y);
    }
    __syncthreads();

    // ---- stage 3 epilogue: base = pooled@W3[256:] + bc; BN2+relu -> h2T ----
    {
        ull base = 0ull;
        #pragma unroll 4
        for (int c = 0; c < D2; ++c) {
            ull wb = *(const ull*)(W3 + (size_t)(D2 + c) * D2 + 2 * t);
            float pc = sm.m.vec[c];
            base = ffma2(wb, pack2(pc, pc), base);
        }
        float bx, by;
        unpack2(base, bx, by);
        float2 bcv = *(const float2*)(g_bc + 2 * t);
        bx += bcv.x; by += bcv.y;

        float2 gg = *(const float2*)(g2  + 2 * t);
        float2 vv = *(const float2*)(v2  + 2 * t);
        float2 mm = *(const float2*)(m2  + 2 * t);
        float2 ee = *(const float2*)(be2 + 2 * t);
        float s0 = gg.x * rsqrtf(vv.x + 1e-5f);
        float s1 = gg.y * rsqrtf(vv.y + 1e-5f);
        float sh0 = ee.x - mm.x * s0;
        float sh1 = ee.y - mm.y * s1;
        float* r0 = sm.m.h2T + (2 * t) * PP;
        float* r1 = sm.m.h2T + (2 * t + 1) * PP;
        #pragma unroll
        for (int q = 0; q < 10; ++q) {
            float a, b;
            unpack2(a3c0[q], a, b);
            *(float2*)&r0[2 * q] =
                make_float2(fmaxf((a + bx) * s0 + sh0, 0.0f),
                            fmaxf((b + bx) * s0 + sh0, 0.0f));
            unpack2(a3c1[q], a, b);
            *(float2*)&r1[2 * q] =
                make_float2(fmaxf((a + by) * s1 + sh1, 0.0f),
                            fmaxf((b + by) * s1 + sh1, 0.0f));
        }
    }
    __syncthreads();

    // ---- stage 4: h2(20x256)@W4+b4 -> max_p -> +type_emb -> out ----
    {
        ull acc0[10], acc1[10];
        #pragma unroll
        for (int q = 0; q < 10; ++q) { acc0[q] = 0ull; acc1[q] = 0ull; }
        #pragma unroll 2
        for (int c = 0; c < D2; ++c) {
            float2 w = *(const float2*)(W4 + c * D2 + 2 * t);
            ull w0 = pack2(w.x, w.x);
            ull w1 = pack2(w.y, w.y);
            const ulonglong2* hv = (const ulonglong2*)(sm.m.h2T + c * PP);
            #pragma unroll
            for (int q = 0; q < 5; ++q) {
                ulonglong2 h = hv[q];
                acc0[2 * q]     = ffma2(h.x, w0, acc0[2 * q]);
                acc0[2 * q + 1] = ffma2(h.y, w0, acc0[2 * q + 1]);
                acc1[2 * q]     = ffma2(h.x, w1, acc1[2 * q]);
                acc1[2 * q + 1] = ffma2(h.y, w1, acc1[2 * q + 1]);
            }
        }
        float2 bb = *(const float2*)(b4 + 2 * t);
        float mx0 = -FLT_MAX, mx1 = -FLT_MAX;
        #pragma unroll
        for (int q = 0; q < 10; ++q) {
            float a, b;
            unpack2(acc0[q], a, b); mx0 = fmaxf(mx0, fmaxf(a, b));
            unpack2(acc1[q], a, b); mx1 = fmaxf(mx1, fmaxf(a, b));
        }
        int lb = label[idx];
        float2 tv = *(const float2*)(temb + (size_t)lb * D2 + 2 * t);
        *(float2*)&feats_out[(size_t)idx * D2 + 2 * t] =
            make_float2(mx0 + bb.x + tv.x, mx1 + bb.y + tv.y);
    }
}

extern "C" void kernel_launch(void* const* d_in, const int* in_sizes, int n_in,
                              void* d_out, int out_size) {
    (void)in_sizes; (void)n_in; (void)out_size;

    const float* tgt   = (const float*)d_in[0];
    const int*   label = (const int*)d_in[1];
    const void*  maskp = d_in[2];
    const float* W1  = (const float*)d_in[3];
    const float* b1  = (const float*)d_in[4];
    const float* g1  = (const float*)d_in[5];
    const float* be1 = (const float*)d_in[6];
    const float* m1  = (const float*)d_in[7];
    const float* v1  = (const float*)d_in[8];
    const float* W2  = (const float*)d_in[9];
    const float* b2  = (const float*)d_in[10];
    const float* W3  = (const float*)d_in[11];
    const float* b3  = (const float*)d_in[12];
    const float* g2  = (const float*)d_in[13];
    const float* be2 = (const float*)d_in[14];
    const float* m2  = (const float*)d_in[15];
    const float* v2  = (const float*)d_in[16];
    const float* W4  = (const float*)d_in[17];
    const float* b4  = (const float*)d_in[18];
    const float* temb = (const float*)d_in[19];
    const float* Wp1 = (const float*)d_in[20];
    const float* bp1 = (const float*)d_in[21];
    const float* Wp2 = (const float*)d_in[22];
    const float* bp2 = (const float*)d_in[23];
    const float* pcr = (const float*)d_in[24];

    precompute_w23_kernel<<<129, 256>>>(W2, W3, b2, b3);
    build_active_kernel<<<BN_TOTAL / 256, 256>>>(maskp);
    map_encoder_kernel<<<17 * (BN_TOTAL / 16), 128>>>(
        tgt, label, maskp,
        W1, b1, g1, be1, m1, v1,
        W2, b2, W3, g2, be2, m2, v2,
        W4, b4, temb, Wp1, bp1, Wp2, bp2, pcr,
        (float*)d_out);
}